// round 1
// baseline (speedup 1.0000x reference)
#include <cuda_runtime.h>
#include <math.h>

// Problem constants (fixed shapes for this problem)
#define BB      8192
#define IN_DIM  1024
#define MEM_DIM 1024
#define CTX_DIM 1024
#define NGATE   3072   // 3*MEM

// ---------------------------------------------------------------------------
// Device scratch (allocation-free rule: __device__ globals)
// ---------------------------------------------------------------------------
__device__ float g_w1 [CTX_DIM * IN_DIM];    // wv @ ip_w
__device__ float g_w2 [CTX_DIM * IN_DIM];    // out_proj_w @ g_w1
__device__ float g_wgi[NGATE   * IN_DIM];    // gru_w_ih @ g_w2
__device__ float g_b1 [CTX_DIM];
__device__ float g_b2 [CTX_DIM];
__device__ float g_bgi[NGATE];
__device__ float g_gi [BB * NGATE];          // input @ g_wgi^T + g_bgi
__device__ float g_gh [BB * NGATE];          // gated @ w_hh^T + b_hh
__device__ float g_fg [BB * MEM_DIM];        // forget-gate preact
__device__ float g_gated[BB * MEM_DIM];      // prev * sigmoid(fg)
__device__ float g_upd[BB * MEM_DIM];        // GRU output
__device__ float g_og [BB * MEM_DIM];        // output-gate preact

__device__ __forceinline__ float sigmoidf_(float x) {
    return 1.0f / (1.0f + expf(-x));
}

// ---------------------------------------------------------------------------
// Tiled SGEMM.
//   TRANS_B = true :  C[M,N] = A[M,K] * B^T   with B stored [N,K] row-major
//   TRANS_B = false:  C[M,N] = A[M,K] * B     with B stored [K,N] row-major
// Optional bias[n] add, optional accumulate into existing C.
// All of M,N,K are multiples of 128 here; no bounds checks needed.
// BM=BN=128, BK=16, 256 threads, 8x8 per thread.
// ---------------------------------------------------------------------------
template <bool TRANS_B>
__global__ __launch_bounds__(256, 2)
void sgemm_kernel(const float* __restrict__ A, int lda,
                  const float* __restrict__ B, int ldb,
                  const float* __restrict__ bias,
                  float* __restrict__ C, int ldc,
                  int M, int N, int K, int accumulate)
{
    constexpr int BM = 128, BN = 128, BK = 16;
    __shared__ float As[BK][BM];
    __shared__ float Bs[BK][BN];

    const int bx  = blockIdx.x;           // N tile
    const int by  = blockIdx.y;           // M tile
    const int tid = threadIdx.x;
    const int tx  = tid & 15;             // 0..15 -> 8 cols each
    const int ty  = tid >> 4;             // 0..15 -> 8 rows each

    // A load: transpose into As[k][m]
    const int arow  = tid >> 2;           // 0..63
    const int acol  = (tid & 3) * 4;      // 0,4,8,12
    // B load indices
    const int btrow = tid >> 2;           // TRANS_B path (same as A)
    const int btcol = (tid & 3) * 4;
    const int bnrow = tid >> 5;           // NN path: 0..7
    const int bncol = (tid & 31) * 4;     // 0..124

    const float* Ab = A + (size_t)(by * BM) * lda;
    const float* Bt = TRANS_B ? (B + (size_t)(bx * BN) * ldb) : B;

    float acc[8][8];
#pragma unroll
    for (int i = 0; i < 8; i++)
#pragma unroll
        for (int j = 0; j < 8; j++) acc[i][j] = 0.0f;

    for (int k0 = 0; k0 < K; k0 += BK) {
        // ---- load A tile (transposed) ----
#pragma unroll
        for (int i = 0; i < 2; i++) {
            float4 v = *(const float4*)(Ab + (size_t)(arow + i * 64) * lda + k0 + acol);
            As[acol + 0][arow + i * 64] = v.x;
            As[acol + 1][arow + i * 64] = v.y;
            As[acol + 2][arow + i * 64] = v.z;
            As[acol + 3][arow + i * 64] = v.w;
        }
        // ---- load B tile ----
        if (TRANS_B) {
#pragma unroll
            for (int i = 0; i < 2; i++) {
                float4 v = *(const float4*)(Bt + (size_t)(btrow + i * 64) * ldb + k0 + btcol);
                Bs[btcol + 0][btrow + i * 64] = v.x;
                Bs[btcol + 1][btrow + i * 64] = v.y;
                Bs[btcol + 2][btrow + i * 64] = v.z;
                Bs[btcol + 3][btrow + i * 64] = v.w;
            }
        } else {
#pragma unroll
            for (int i = 0; i < 2; i++) {
                float4 v = *(const float4*)(B + (size_t)(k0 + bnrow + i * 8) * ldb + bx * BN + bncol);
                *(float4*)&Bs[bnrow + i * 8][bncol] = v;
            }
        }
        __syncthreads();

        // ---- compute ----
#pragma unroll
        for (int kk = 0; kk < BK; kk++) {
            float4 a0 = *(const float4*)&As[kk][ty * 8];
            float4 a1 = *(const float4*)&As[kk][ty * 8 + 4];
            float4 b0 = *(const float4*)&Bs[kk][tx * 8];
            float4 b1 = *(const float4*)&Bs[kk][tx * 8 + 4];
            float a[8] = {a0.x, a0.y, a0.z, a0.w, a1.x, a1.y, a1.z, a1.w};
            float b[8] = {b0.x, b0.y, b0.z, b0.w, b1.x, b1.y, b1.z, b1.w};
#pragma unroll
            for (int i = 0; i < 8; i++)
#pragma unroll
                for (int j = 0; j < 8; j++)
                    acc[i][j] = fmaf(a[i], b[j], acc[i][j]);
        }
        __syncthreads();
    }

    // ---- epilogue ----
    const int row0 = by * BM + ty * 8;
    const int col0 = bx * BN + tx * 8;
    float bv[8];
#pragma unroll
    for (int j = 0; j < 8; j++) bv[j] = bias ? bias[col0 + j] : 0.0f;

    float* Cp = C + (size_t)row0 * ldc + col0;
    if (accumulate) {
#pragma unroll
        for (int i = 0; i < 8; i++)
#pragma unroll
            for (int j = 0; j < 8; j++)
                Cp[(size_t)i * ldc + j] += acc[i][j] + bv[j];
    } else {
#pragma unroll
        for (int i = 0; i < 8; i++)
#pragma unroll
            for (int j = 0; j < 8; j++)
                Cp[(size_t)i * ldc + j] = acc[i][j] + bv[j];
    }
}

// ---------------------------------------------------------------------------
// GEMV: y[i] = sum_k W[i,k] * x[k] + b[i]   (W row-major [N,K], one warp/row)
// ---------------------------------------------------------------------------
__global__ void gemv_kernel(const float* __restrict__ W, int ldw,
                            const float* __restrict__ x,
                            const float* __restrict__ b,
                            float* __restrict__ y, int N, int K)
{
    int row  = blockIdx.x * 8 + (threadIdx.x >> 5);
    int lane = threadIdx.x & 31;
    if (row >= N) return;
    float s = 0.0f;
    for (int k = lane; k < K; k += 32) s += W[(size_t)row * ldw + k] * x[k];
#pragma unroll
    for (int o = 16; o > 0; o >>= 1) s += __shfl_down_sync(0xFFFFFFFFu, s, o);
    if (lane == 0) y[row] = s + (b ? b[row] : 0.0f);
}

// ---------------------------------------------------------------------------
// Elementwise kernels
// ---------------------------------------------------------------------------
__global__ void ew_gate_kernel(const float* __restrict__ prev,
                               const float* __restrict__ fgpre,
                               float* __restrict__ gated, int n)
{
    int idx = blockIdx.x * blockDim.x + threadIdx.x;
    if (idx < n) gated[idx] = prev[idx] * sigmoidf_(fgpre[idx]);
}

__global__ void ew_gru_kernel(const float* __restrict__ gi,
                              const float* __restrict__ gh,
                              const float* __restrict__ gated,
                              float* __restrict__ upd, int n)
{
    int idx = blockIdx.x * blockDim.x + threadIdx.x;
    if (idx >= n) return;
    int b = idx / MEM_DIM;
    int j = idx - b * MEM_DIM;
    size_t base = (size_t)b * NGATE;
    float r = sigmoidf_(gi[base + j]               + gh[base + j]);
    float z = sigmoidf_(gi[base + MEM_DIM + j]     + gh[base + MEM_DIM + j]);
    float nn = tanhf  (gi[base + 2 * MEM_DIM + j] + r * gh[base + 2 * MEM_DIM + j]);
    upd[idx] = (1.0f - z) * nn + z * gated[idx];
}

__global__ void ew_out_kernel(const float* __restrict__ upd,
                              const float* __restrict__ ogpre,
                              float* __restrict__ out, int n)
{
    int idx = blockIdx.x * blockDim.x + threadIdx.x;
    if (idx < n) out[idx] = upd[idx] * sigmoidf_(ogpre[idx]);
}

__global__ void fill_ones_kernel(float* __restrict__ out, int n)
{
    int idx = blockIdx.x * blockDim.x + threadIdx.x;
    if (idx < n) out[idx] = 1.0f;
}

// ---------------------------------------------------------------------------
// Launch
// ---------------------------------------------------------------------------
extern "C" void kernel_launch(void* const* d_in, const int* in_sizes, int n_in,
                              void* d_out, int out_size)
{
    const float* input      = (const float*)d_in[0];   // [B, IN]
    const float* prev       = (const float*)d_in[1];   // [B, MEM]
    const float* in_proj_w  = (const float*)d_in[2];   // [3*CTX, CTX]
    const float* in_proj_b  = (const float*)d_in[3];   // [3*CTX]
    const float* out_proj_w = (const float*)d_in[4];   // [CTX, CTX]
    const float* out_proj_b = (const float*)d_in[5];   // [CTX]
    const float* ip_w       = (const float*)d_in[6];   // [CTX, IN]
    const float* ip_b       = (const float*)d_in[7];   // [CTX]
    // d_in[8], d_in[9] = mp_w, mp_b : dead (softmax over single key == 1)
    const float* fg_w       = (const float*)d_in[10];  // [MEM, MEM+IN]
    const float* fg_b       = (const float*)d_in[11];  // [MEM]
    const float* og_w       = (const float*)d_in[12];  // [MEM, MEM]
    const float* og_b       = (const float*)d_in[13];  // [MEM]
    const float* w_ih       = (const float*)d_in[14];  // [3*MEM, CTX]
    const float* b_ih       = (const float*)d_in[15];  // [3*MEM]
    const float* w_hh       = (const float*)d_in[16];  // [3*MEM, MEM]
    const float* b_hh       = (const float*)d_in[17];  // [3*MEM]
    float* out = (float*)d_out;

    // wq/wk dead; only wv / bv matter (attn == v)
    const float* wv = in_proj_w + 2 * CTX_DIM * CTX_DIM;
    const float* bv = in_proj_b + 2 * CTX_DIM;

    float *w1, *w2, *wgi, *b1, *b2, *bgi, *gi, *gh, *fg, *gated, *upd, *og;
    cudaGetSymbolAddress((void**)&w1,    g_w1);
    cudaGetSymbolAddress((void**)&w2,    g_w2);
    cudaGetSymbolAddress((void**)&wgi,   g_wgi);
    cudaGetSymbolAddress((void**)&b1,    g_b1);
    cudaGetSymbolAddress((void**)&b2,    g_b2);
    cudaGetSymbolAddress((void**)&bgi,   g_bgi);
    cudaGetSymbolAddress((void**)&gi,    g_gi);
    cudaGetSymbolAddress((void**)&gh,    g_gh);
    cudaGetSymbolAddress((void**)&fg,    g_fg);
    cudaGetSymbolAddress((void**)&gated, g_gated);
    cudaGetSymbolAddress((void**)&upd,   g_upd);
    cudaGetSymbolAddress((void**)&og,    g_og);

    const dim3 blk(256);

    // ---- bias folds (tiny) ----
    gemv_kernel<<<CTX_DIM / 8, 256>>>(wv,         CTX_DIM, ip_b, bv,         b1,  CTX_DIM, CTX_DIM);
    gemv_kernel<<<CTX_DIM / 8, 256>>>(out_proj_w, CTX_DIM, b1,   out_proj_b, b2,  CTX_DIM, CTX_DIM);
    gemv_kernel<<<NGATE   / 8, 256>>>(w_ih,       CTX_DIM, b2,   b_ih,       bgi, NGATE,   CTX_DIM);

    // ---- weight folds:  wgi = w_ih @ out_proj_w @ wv @ ip_w ----
    sgemm_kernel<false><<<dim3(IN_DIM / 128, CTX_DIM / 128), blk>>>(
        wv, CTX_DIM, ip_w, IN_DIM, nullptr, w1, IN_DIM, CTX_DIM, IN_DIM, CTX_DIM, 0);
    sgemm_kernel<false><<<dim3(IN_DIM / 128, CTX_DIM / 128), blk>>>(
        out_proj_w, CTX_DIM, w1, IN_DIM, nullptr, w2, IN_DIM, CTX_DIM, IN_DIM, CTX_DIM, 0);
    sgemm_kernel<false><<<dim3(IN_DIM / 128, NGATE / 128), blk>>>(
        w_ih, CTX_DIM, w2, IN_DIM, nullptr, wgi, IN_DIM, NGATE, IN_DIM, CTX_DIM, 0);

    // ---- GI = input @ wgi^T + bgi     [B, 3*MEM] ----
    sgemm_kernel<true><<<dim3(NGATE / 128, BB / 128), blk>>>(
        input, IN_DIM, wgi, IN_DIM, bgi, gi, NGATE, BB, NGATE, IN_DIM, 0);

    // ---- forget gate: fg = prev @ fgA^T + input @ fgB^T + fg_b ----
    sgemm_kernel<true><<<dim3(MEM_DIM / 128, BB / 128), blk>>>(
        prev, MEM_DIM, fg_w, MEM_DIM + IN_DIM, fg_b, fg, MEM_DIM, BB, MEM_DIM, MEM_DIM, 0);
    sgemm_kernel<true><<<dim3(MEM_DIM / 128, BB / 128), blk>>>(
        input, IN_DIM, fg_w + MEM_DIM, MEM_DIM + IN_DIM, nullptr, fg, MEM_DIM, BB, MEM_DIM, IN_DIM, 1);

    ew_gate_kernel<<<(BB * MEM_DIM) / 256, 256>>>(prev, fg, gated, BB * MEM_DIM);

    // ---- GH = gated @ w_hh^T + b_hh   [B, 3*MEM] ----
    sgemm_kernel<true><<<dim3(NGATE / 128, BB / 128), blk>>>(
        gated, MEM_DIM, w_hh, MEM_DIM, b_hh, gh, NGATE, BB, NGATE, MEM_DIM, 0);

    ew_gru_kernel<<<(BB * MEM_DIM) / 256, 256>>>(gi, gh, gated, upd, BB * MEM_DIM);

    // ---- output gate ----
    sgemm_kernel<true><<<dim3(MEM_DIM / 128, BB / 128), blk>>>(
        upd, MEM_DIM, og_w, MEM_DIM, og_b, og, MEM_DIM, BB, MEM_DIM, MEM_DIM, 0);

    ew_out_kernel<<<(BB * MEM_DIM) / 256, 256>>>(upd, og, out, BB * MEM_DIM);

    // ---- attention weights output: softmax over a single key == 1.0 ----
    int tail = out_size - BB * MEM_DIM;
    if (tail > 0)
        fill_ones_kernel<<<(tail + 255) / 256, 256>>>(out + BB * MEM_DIM, tail);
}

// round 2
// speedup vs baseline: 1.0002x; 1.0002x over previous
#include <cuda_runtime.h>
#include <math.h>

// Problem constants (fixed shapes for this problem)
#define BB      8192
#define IN_DIM  1024
#define MEM_DIM 1024
#define CTX_DIM 1024
#define NGATE   3072   // 3*MEM

// ---------------------------------------------------------------------------
// Device scratch (allocation-free rule: __device__ globals)
// ---------------------------------------------------------------------------
__device__ float g_w1 [CTX_DIM * IN_DIM];    // wv @ ip_w
__device__ float g_w2 [CTX_DIM * IN_DIM];    // out_proj_w @ g_w1
__device__ float g_wgi[NGATE   * IN_DIM];    // gru_w_ih @ g_w2
__device__ float g_b1 [CTX_DIM];
__device__ float g_b2 [CTX_DIM];
__device__ float g_bgi[NGATE];
__device__ float g_gi [BB * NGATE];          // input @ g_wgi^T + g_bgi
__device__ float g_gh [BB * NGATE];          // gated @ w_hh^T + b_hh
__device__ float g_fg [BB * MEM_DIM];        // forget-gate preact
__device__ float g_gated[BB * MEM_DIM];      // prev * sigmoid(fg)
__device__ float g_upd[BB * MEM_DIM];        // GRU output
__device__ float g_og [BB * MEM_DIM];        // output-gate preact

__device__ __forceinline__ float sigmoidf_(float x) {
    return 1.0f / (1.0f + expf(-x));
}

// ---------------------------------------------------------------------------
// Tiled SGEMM.
//   TRANS_B = true :  C[M,N] = A[M,K] * B^T   with B stored [N,K] row-major
//   TRANS_B = false:  C[M,N] = A[M,K] * B     with B stored [K,N] row-major
// Optional bias[n] add, optional accumulate into existing C.
// All of M,N,K are multiples of 128 here; no bounds checks needed.
// BM=BN=128, BK=16, 256 threads, 8x8 per thread.
// ---------------------------------------------------------------------------
template <bool TRANS_B>
__global__ __launch_bounds__(256, 2)
void sgemm_kernel(const float* __restrict__ A, int lda,
                  const float* __restrict__ B, int ldb,
                  const float* __restrict__ bias,
                  float* __restrict__ C, int ldc,
                  int M, int N, int K, int accumulate)
{
    constexpr int BM = 128, BN = 128, BK = 16;
    __shared__ float As[BK][BM];
    __shared__ float Bs[BK][BN];

    const int bx  = blockIdx.x;           // N tile
    const int by  = blockIdx.y;           // M tile
    const int tid = threadIdx.x;
    const int tx  = tid & 15;             // 0..15 -> 8 cols each
    const int ty  = tid >> 4;             // 0..15 -> 8 rows each

    // A load: transpose into As[k][m]
    const int arow  = tid >> 2;           // 0..63
    const int acol  = (tid & 3) * 4;      // 0,4,8,12
    // B load indices
    const int btrow = tid >> 2;           // TRANS_B path (same as A)
    const int btcol = (tid & 3) * 4;
    const int bnrow = tid >> 5;           // NN path: 0..7
    const int bncol = (tid & 31) * 4;     // 0..124

    const float* Ab = A + (size_t)(by * BM) * lda;
    const float* Bt = TRANS_B ? (B + (size_t)(bx * BN) * ldb) : B;

    float acc[8][8];
#pragma unroll
    for (int i = 0; i < 8; i++)
#pragma unroll
        for (int j = 0; j < 8; j++) acc[i][j] = 0.0f;

    for (int k0 = 0; k0 < K; k0 += BK) {
        // ---- load A tile (transposed) ----
#pragma unroll
        for (int i = 0; i < 2; i++) {
            float4 v = *(const float4*)(Ab + (size_t)(arow + i * 64) * lda + k0 + acol);
            As[acol + 0][arow + i * 64] = v.x;
            As[acol + 1][arow + i * 64] = v.y;
            As[acol + 2][arow + i * 64] = v.z;
            As[acol + 3][arow + i * 64] = v.w;
        }
        // ---- load B tile ----
        if (TRANS_B) {
#pragma unroll
            for (int i = 0; i < 2; i++) {
                float4 v = *(const float4*)(Bt + (size_t)(btrow + i * 64) * ldb + k0 + btcol);
                Bs[btcol + 0][btrow + i * 64] = v.x;
                Bs[btcol + 1][btrow + i * 64] = v.y;
                Bs[btcol + 2][btrow + i * 64] = v.z;
                Bs[btcol + 3][btrow + i * 64] = v.w;
            }
        } else {
#pragma unroll
            for (int i = 0; i < 2; i++) {
                float4 v = *(const float4*)(B + (size_t)(k0 + bnrow + i * 8) * ldb + bx * BN + bncol);
                *(float4*)&Bs[bnrow + i * 8][bncol] = v;
            }
        }
        __syncthreads();

        // ---- compute ----
#pragma unroll
        for (int kk = 0; kk < BK; kk++) {
            float4 a0 = *(const float4*)&As[kk][ty * 8];
            float4 a1 = *(const float4*)&As[kk][ty * 8 + 4];
            float4 b0 = *(const float4*)&Bs[kk][tx * 8];
            float4 b1 = *(const float4*)&Bs[kk][tx * 8 + 4];
            float a[8] = {a0.x, a0.y, a0.z, a0.w, a1.x, a1.y, a1.z, a1.w};
            float b[8] = {b0.x, b0.y, b0.z, b0.w, b1.x, b1.y, b1.z, b1.w};
#pragma unroll
            for (int i = 0; i < 8; i++)
#pragma unroll
                for (int j = 0; j < 8; j++)
                    acc[i][j] = fmaf(a[i], b[j], acc[i][j]);
        }
        __syncthreads();
    }

    // ---- epilogue ----
    const int row0 = by * BM + ty * 8;
    const int col0 = bx * BN + tx * 8;
    float bv[8];
#pragma unroll
    for (int j = 0; j < 8; j++) bv[j] = bias ? bias[col0 + j] : 0.0f;

    float* Cp = C + (size_t)row0 * ldc + col0;
    if (accumulate) {
#pragma unroll
        for (int i = 0; i < 8; i++)
#pragma unroll
            for (int j = 0; j < 8; j++)
                Cp[(size_t)i * ldc + j] += acc[i][j] + bv[j];
    } else {
#pragma unroll
        for (int i = 0; i < 8; i++)
#pragma unroll
            for (int j = 0; j < 8; j++)
                Cp[(size_t)i * ldc + j] = acc[i][j] + bv[j];
    }
}

// ---------------------------------------------------------------------------
// GEMV: y[i] = sum_k W[i,k] * x[k] + b[i]   (W row-major [N,K], one warp/row)
// ---------------------------------------------------------------------------
__global__ void gemv_kernel(const float* __restrict__ W, int ldw,
                            const float* __restrict__ x,
                            const float* __restrict__ b,
                            float* __restrict__ y, int N, int K)
{
    int row  = blockIdx.x * 8 + (threadIdx.x >> 5);
    int lane = threadIdx.x & 31;
    if (row >= N) return;
    float s = 0.0f;
    for (int k = lane; k < K; k += 32) s += W[(size_t)row * ldw + k] * x[k];
#pragma unroll
    for (int o = 16; o > 0; o >>= 1) s += __shfl_down_sync(0xFFFFFFFFu, s, o);
    if (lane == 0) y[row] = s + (b ? b[row] : 0.0f);
}

// ---------------------------------------------------------------------------
// Elementwise kernels
// ---------------------------------------------------------------------------
__global__ void ew_gate_kernel(const float* __restrict__ prev,
                               const float* __restrict__ fgpre,
                               float* __restrict__ gated, int n)
{
    int idx = blockIdx.x * blockDim.x + threadIdx.x;
    if (idx < n) gated[idx] = prev[idx] * sigmoidf_(fgpre[idx]);
}

__global__ void ew_gru_kernel(const float* __restrict__ gi,
                              const float* __restrict__ gh,
                              const float* __restrict__ gated,
                              float* __restrict__ upd, int n)
{
    int idx = blockIdx.x * blockDim.x + threadIdx.x;
    if (idx >= n) return;
    int b = idx / MEM_DIM;
    int j = idx - b * MEM_DIM;
    size_t base = (size_t)b * NGATE;
    float r = sigmoidf_(gi[base + j]               + gh[base + j]);
    float z = sigmoidf_(gi[base + MEM_DIM + j]     + gh[base + MEM_DIM + j]);
    float nn = tanhf  (gi[base + 2 * MEM_DIM + j] + r * gh[base + 2 * MEM_DIM + j]);
    upd[idx] = (1.0f - z) * nn + z * gated[idx];
}

__global__ void ew_out_kernel(const float* __restrict__ upd,
                              const float* __restrict__ ogpre,
                              float* __restrict__ out, int n)
{
    int idx = blockIdx.x * blockDim.x + threadIdx.x;
    if (idx < n) out[idx] = upd[idx] * sigmoidf_(ogpre[idx]);
}

__global__ void fill_ones_kernel(float* __restrict__ out, int n)
{
    int idx = blockIdx.x * blockDim.x + threadIdx.x;
    if (idx < n) out[idx] = 1.0f;
}

// ---------------------------------------------------------------------------
// Launch
// ---------------------------------------------------------------------------
extern "C" void kernel_launch(void* const* d_in, const int* in_sizes, int n_in,
                              void* d_out, int out_size)
{
    const float* input      = (const float*)d_in[0];   // [B, IN]
    const float* prev       = (const float*)d_in[1];   // [B, MEM]
    const float* in_proj_w  = (const float*)d_in[2];   // [3*CTX, CTX]
    const float* in_proj_b  = (const float*)d_in[3];   // [3*CTX]
    const float* out_proj_w = (const float*)d_in[4];   // [CTX, CTX]
    const float* out_proj_b = (const float*)d_in[5];   // [CTX]
    const float* ip_w       = (const float*)d_in[6];   // [CTX, IN]
    const float* ip_b       = (const float*)d_in[7];   // [CTX]
    // d_in[8], d_in[9] = mp_w, mp_b : dead (softmax over single key == 1)
    const float* fg_w       = (const float*)d_in[10];  // [MEM, MEM+IN]
    const float* fg_b       = (const float*)d_in[11];  // [MEM]
    const float* og_w       = (const float*)d_in[12];  // [MEM, MEM]
    const float* og_b       = (const float*)d_in[13];  // [MEM]
    const float* w_ih       = (const float*)d_in[14];  // [3*MEM, CTX]
    const float* b_ih       = (const float*)d_in[15];  // [3*MEM]
    const float* w_hh       = (const float*)d_in[16];  // [3*MEM, MEM]
    const float* b_hh       = (const float*)d_in[17];  // [3*MEM]
    float* out = (float*)d_out;

    // wq/wk dead; only wv / bv matter (attn == v)
    const float* wv = in_proj_w + 2 * CTX_DIM * CTX_DIM;
    const float* bv = in_proj_b + 2 * CTX_DIM;

    float *w1, *w2, *wgi, *b1, *b2, *bgi, *gi, *gh, *fg, *gated, *upd, *og;
    cudaGetSymbolAddress((void**)&w1,    g_w1);
    cudaGetSymbolAddress((void**)&w2,    g_w2);
    cudaGetSymbolAddress((void**)&wgi,   g_wgi);
    cudaGetSymbolAddress((void**)&b1,    g_b1);
    cudaGetSymbolAddress((void**)&b2,    g_b2);
    cudaGetSymbolAddress((void**)&bgi,   g_bgi);
    cudaGetSymbolAddress((void**)&gi,    g_gi);
    cudaGetSymbolAddress((void**)&gh,    g_gh);
    cudaGetSymbolAddress((void**)&fg,    g_fg);
    cudaGetSymbolAddress((void**)&gated, g_gated);
    cudaGetSymbolAddress((void**)&upd,   g_upd);
    cudaGetSymbolAddress((void**)&og,    g_og);

    const dim3 blk(256);

    // ---- bias folds (tiny) ----
    gemv_kernel<<<CTX_DIM / 8, 256>>>(wv,         CTX_DIM, ip_b, bv,         b1,  CTX_DIM, CTX_DIM);
    gemv_kernel<<<CTX_DIM / 8, 256>>>(out_proj_w, CTX_DIM, b1,   out_proj_b, b2,  CTX_DIM, CTX_DIM);
    gemv_kernel<<<NGATE   / 8, 256>>>(w_ih,       CTX_DIM, b2,   b_ih,       bgi, NGATE,   CTX_DIM);

    // ---- weight folds:  wgi = w_ih @ out_proj_w @ wv @ ip_w ----
    sgemm_kernel<false><<<dim3(IN_DIM / 128, CTX_DIM / 128), blk>>>(
        wv, CTX_DIM, ip_w, IN_DIM, nullptr, w1, IN_DIM, CTX_DIM, IN_DIM, CTX_DIM, 0);
    sgemm_kernel<false><<<dim3(IN_DIM / 128, CTX_DIM / 128), blk>>>(
        out_proj_w, CTX_DIM, w1, IN_DIM, nullptr, w2, IN_DIM, CTX_DIM, IN_DIM, CTX_DIM, 0);
    sgemm_kernel<false><<<dim3(IN_DIM / 128, NGATE / 128), blk>>>(
        w_ih, CTX_DIM, w2, IN_DIM, nullptr, wgi, IN_DIM, NGATE, IN_DIM, CTX_DIM, 0);

    // ---- GI = input @ wgi^T + bgi     [B, 3*MEM] ----
    sgemm_kernel<true><<<dim3(NGATE / 128, BB / 128), blk>>>(
        input, IN_DIM, wgi, IN_DIM, bgi, gi, NGATE, BB, NGATE, IN_DIM, 0);

    // ---- forget gate: fg = prev @ fgA^T + input @ fgB^T + fg_b ----
    sgemm_kernel<true><<<dim3(MEM_DIM / 128, BB / 128), blk>>>(
        prev, MEM_DIM, fg_w, MEM_DIM + IN_DIM, fg_b, fg, MEM_DIM, BB, MEM_DIM, MEM_DIM, 0);
    sgemm_kernel<true><<<dim3(MEM_DIM / 128, BB / 128), blk>>>(
        input, IN_DIM, fg_w + MEM_DIM, MEM_DIM + IN_DIM, nullptr, fg, MEM_DIM, BB, MEM_DIM, IN_DIM, 1);

    ew_gate_kernel<<<(BB * MEM_DIM) / 256, 256>>>(prev, fg, gated, BB * MEM_DIM);

    // ---- GH = gated @ w_hh^T + b_hh   [B, 3*MEM] ----
    sgemm_kernel<true><<<dim3(NGATE / 128, BB / 128), blk>>>(
        gated, MEM_DIM, w_hh, MEM_DIM, b_hh, gh, NGATE, BB, NGATE, MEM_DIM, 0);

    ew_gru_kernel<<<(BB * MEM_DIM) / 256, 256>>>(gi, gh, gated, upd, BB * MEM_DIM);

    // ---- output gate ----
    sgemm_kernel<true><<<dim3(MEM_DIM / 128, BB / 128), blk>>>(
        upd, MEM_DIM, og_w, MEM_DIM, og_b, og, MEM_DIM, BB, MEM_DIM, MEM_DIM, 0);

    ew_out_kernel<<<(BB * MEM_DIM) / 256, 256>>>(upd, og, out, BB * MEM_DIM);

    // ---- attention weights output: softmax over a single key == 1.0 ----
    int tail = out_size - BB * MEM_DIM;
    if (tail > 0)
        fill_ones_kernel<<<(tail + 255) / 256, 256>>>(out + BB * MEM_DIM, tail);
}

// round 4
// speedup vs baseline: 2.6751x; 2.6747x over previous
#include <cuda_runtime.h>
#include <math.h>
#include <stdint.h>

#define BB      8192
#define IN_DIM  1024
#define MEM_DIM 1024
#define CTX_DIM 1024
#define NGATE   3072

// ---- GEMM tiling ----
#define BM 128
#define BN 128
#define BK 32
#define PAD 36                    // floats per smem row (16B-aligned, conflict-free frags)
#define STG 3
#define TILE_F (BM * PAD)         // floats per A or B tile
#define STAGE_F (2 * TILE_F)
#define SMEM_DYN (STG * STAGE_F * 4)   // 110592 bytes

// ---------------------------------------------------------------------------
// Device scratch (__device__ globals; allocation-free rule)
// ---------------------------------------------------------------------------
__device__ __align__(256) float g_ipT [IN_DIM * CTX_DIM];
__device__ __align__(256) float g_m1t [IN_DIM * CTX_DIM];
__device__ __align__(256) float g_m2t [IN_DIM * CTX_DIM];
__device__ __align__(256) float g_wgi [NGATE  * IN_DIM];
__device__ __align__(256) float g_sAh [NGATE  * CTX_DIM];
__device__ __align__(256) float g_sAl [NGATE  * CTX_DIM];
__device__ __align__(256) float g_sBh [CTX_DIM * CTX_DIM];
__device__ __align__(256) float g_sBl [CTX_DIM * CTX_DIM];
__device__ __align__(256) float g_b1  [CTX_DIM];
__device__ __align__(256) float g_b2  [CTX_DIM];
__device__ __align__(256) float g_bgi [NGATE];
__device__ __align__(256) float g_rin  [(size_t)BB * IN_DIM];
__device__ __align__(256) float g_rprev[(size_t)BB * MEM_DIM];
__device__ __align__(256) float g_rfgw [MEM_DIM * (MEM_DIM + IN_DIM)];
__device__ __align__(256) float g_rwhh [NGATE * MEM_DIM];
__device__ __align__(256) float g_rogw [MEM_DIM * MEM_DIM];
__device__ __align__(256) float g_gi   [(size_t)BB * NGATE];
__device__ __align__(256) float g_gh   [(size_t)BB * NGATE];
__device__ __align__(256) float g_gated [(size_t)BB * MEM_DIM];
__device__ __align__(256) float g_gatedr[(size_t)BB * MEM_DIM];
__device__ __align__(256) float g_upd   [(size_t)BB * MEM_DIM];
__device__ __align__(256) float g_updr  [(size_t)BB * MEM_DIM];

// ---------------------------------------------------------------------------
// Helpers
// ---------------------------------------------------------------------------
__device__ __forceinline__ uint32_t smem_u32(const void* p) {
    uint32_t a;
    asm("{ .reg .u64 t; cvta.to.shared.u64 t, %1; cvt.u32.u64 %0, t; }" : "=r"(a) : "l"(p));
    return a;
}
__device__ __forceinline__ float sigmoidf_(float x) { return 1.0f / (1.0f + expf(-x)); }
__device__ __forceinline__ float rna_tf32(float x) {
    uint32_t u;
    asm("cvt.rna.tf32.f32 %0, %1;" : "=r"(u) : "f"(x));
    return __uint_as_float(u);
}

// ---------------------------------------------------------------------------
// Segmented tf32 mma.sync GEMM:
//   pre[m,n] = sum_seg sum_k A_seg[m,k]*B_seg[n,k]  (+bias[n])
//   mode 0: C = pre (rounded to tf32 if round_out)
//   mode 1: C = mul * sigmoid(pre)
//   mode 2: C = mul * sigmoid(pre), C2 = rna_tf32(C)
// A_seg [M,K] row-major, B_seg [N,K] row-major. M,N mult of 128, K_seg mult of 32.
// ---------------------------------------------------------------------------
struct Seg { const float* A; int lda; const float* B; int ldb; int K; };

__global__ __launch_bounds__(256, 2)
void tf32_gemm(Seg s0, Seg s1, Seg s2,
               const float* __restrict__ bias,
               const float* __restrict__ mul,
               float* __restrict__ C, float* __restrict__ C2,
               int ldc, int mode, int round_out)
{
    extern __shared__ float smf[];
    const uint32_t sbase = smem_u32(smf);

    const int tid = threadIdx.x;
    const int wid = tid >> 5, lid = tid & 31;
    const int g = lid >> 2, tg = lid & 3;
    const int wm = wid & 3, wn = wid >> 2;          // warp grid 4(M) x 2(N)
    const int row0 = blockIdx.y * BM, col0 = blockIdx.x * BN;

    const int e0 = s0.K / BK;
    const int e1 = e0 + s1.K / BK;
    const int niter = e1 + s2.K / BK;

    const float* A0 = s0.A + (size_t)row0 * s0.lda;
    const float* B0 = s0.B + (size_t)col0 * s0.ldb;
    const float* A1 = s1.A ? s1.A + (size_t)row0 * s1.lda : A0;
    const float* B1 = s1.B ? s1.B + (size_t)col0 * s1.ldb : B0;
    const float* A2 = s2.A ? s2.A + (size_t)row0 * s2.lda : A0;
    const float* B2 = s2.B ? s2.B + (size_t)col0 * s2.ldb : B0;

    auto load_stage = [&](int s, int kc) {
        const float* Ag; const float* Bg; int lda, ldb, k0;
        if (kc < e0)      { Ag = A0; Bg = B0; lda = s0.lda; ldb = s0.ldb; k0 = kc * BK; }
        else if (kc < e1) { Ag = A1; Bg = B1; lda = s1.lda; ldb = s1.ldb; k0 = (kc - e0) * BK; }
        else              { Ag = A2; Bg = B2; lda = s2.lda; ldb = s2.ldb; k0 = (kc - e1) * BK; }
        const uint32_t sa = sbase + (uint32_t)s * STAGE_F * 4;
        const uint32_t sb = sa + TILE_F * 4;
#pragma unroll
        for (int i = 0; i < 4; i++) {
            int c = tid + i * 256, r = c >> 3, ch = c & 7;
            asm volatile("cp.async.cg.shared.global [%0], [%1], 16;"
                :: "r"(sa + (uint32_t)(r * PAD + ch * 4) * 4),
                   "l"(Ag + (size_t)r * lda + k0 + ch * 4) : "memory");
        }
#pragma unroll
        for (int i = 0; i < 4; i++) {
            int c = tid + i * 256, r = c >> 3, ch = c & 7;
            asm volatile("cp.async.cg.shared.global [%0], [%1], 16;"
                :: "r"(sb + (uint32_t)(r * PAD + ch * 4) * 4),
                   "l"(Bg + (size_t)r * ldb + k0 + ch * 4) : "memory");
        }
    };

    float acc[2][8][4];
#pragma unroll
    for (int mt = 0; mt < 2; mt++)
#pragma unroll
        for (int nt = 0; nt < 8; nt++)
#pragma unroll
            for (int e = 0; e < 4; e++) acc[mt][nt][e] = 0.0f;

    // prologue: stages 0..STG-2
    for (int p = 0; p < STG - 1; p++) {
        load_stage(p, p);
        asm volatile("cp.async.commit_group;" ::: "memory");
    }

    for (int it = 0; it < niter; it++) {
        const int pre = it + STG - 1;
        if (pre < niter) load_stage(pre % STG, pre);
        asm volatile("cp.async.commit_group;" ::: "memory");
        asm volatile("cp.async.wait_group %0;" :: "n"(STG - 1) : "memory");
        __syncthreads();

        const float* As = smf + (it % STG) * STAGE_F;
        const float* Bs = As + TILE_F;
#pragma unroll
        for (int kk = 0; kk < 4; kk++) {
            const int k = kk * 8;
            uint32_t af[2][4], bf[8][2];
#pragma unroll
            for (int mt = 0; mt < 2; mt++) {
                const float* ap = As + (wm * 32 + mt * 16 + g) * PAD + k + tg;
                af[mt][0] = __float_as_uint(ap[0]);
                af[mt][1] = __float_as_uint(ap[8 * PAD]);
                af[mt][2] = __float_as_uint(ap[4]);
                af[mt][3] = __float_as_uint(ap[8 * PAD + 4]);
            }
#pragma unroll
            for (int nt = 0; nt < 8; nt++) {
                const float* bp = Bs + (wn * 64 + nt * 8 + g) * PAD + k + tg;
                bf[nt][0] = __float_as_uint(bp[0]);
                bf[nt][1] = __float_as_uint(bp[4]);
            }
#pragma unroll
            for (int mt = 0; mt < 2; mt++)
#pragma unroll
                for (int nt = 0; nt < 8; nt++)
                    asm volatile(
                        "mma.sync.aligned.m16n8k8.row.col.f32.tf32.tf32.f32 "
                        "{%0,%1,%2,%3}, {%4,%5,%6,%7}, {%8,%9}, {%0,%1,%2,%3};"
                        : "+f"(acc[mt][nt][0]), "+f"(acc[mt][nt][1]),
                          "+f"(acc[mt][nt][2]), "+f"(acc[mt][nt][3])
                        : "r"(af[mt][0]), "r"(af[mt][1]), "r"(af[mt][2]), "r"(af[mt][3]),
                          "r"(bf[nt][0]), "r"(bf[nt][1]));
        }
        __syncthreads();   // protect slot (it%STG) before it is reloaded next iter
    }

    // ---- epilogue ----
#pragma unroll
    for (int mt = 0; mt < 2; mt++)
#pragma unroll
        for (int h = 0; h < 2; h++) {
            const int row = row0 + wm * 32 + mt * 16 + g + h * 8;
            float* crow        = C + (size_t)row * ldc + col0 + wn * 64;
            const float* mrow  = mul ? mul + (size_t)row * ldc + col0 + wn * 64 : nullptr;
            float* c2row       = C2 ? C2 + (size_t)row * ldc + col0 + wn * 64 : nullptr;
#pragma unroll
            for (int nt = 0; nt < 8; nt++) {
                const int col = nt * 8 + 2 * tg;
                float v0 = acc[mt][nt][h * 2 + 0];
                float v1 = acc[mt][nt][h * 2 + 1];
                if (bias) {
                    v0 += bias[col0 + wn * 64 + col];
                    v1 += bias[col0 + wn * 64 + col + 1];
                }
                if (mode >= 1) {
                    float2 m = *(const float2*)(mrow + col);
                    v0 = m.x * sigmoidf_(v0);
                    v1 = m.y * sigmoidf_(v1);
                }
                if (mode == 2)
                    *(float2*)(c2row + col) = make_float2(rna_tf32(v0), rna_tf32(v1));
                if (round_out) { v0 = rna_tf32(v0); v1 = rna_tf32(v1); }
                *(float2*)(crow + col) = make_float2(v0, v1);
            }
        }
}

// ---------------------------------------------------------------------------
// Small kernels
// ---------------------------------------------------------------------------
__global__ void transpose_kernel(const float* __restrict__ src, float* __restrict__ dst,
                                 int R, int C)  // src[R,C] -> dst[C,R]
{
    __shared__ float t[32][33];
    int bx = blockIdx.x * 32, by = blockIdx.y * 32;
#pragma unroll
    for (int j = 0; j < 32; j += 8)
        t[threadIdx.y + j][threadIdx.x] = src[(size_t)(by + threadIdx.y + j) * C + bx + threadIdx.x];
    __syncthreads();
#pragma unroll
    for (int j = 0; j < 32; j += 8)
        dst[(size_t)(bx + threadIdx.y + j) * R + by + threadIdx.x] = t[threadIdx.x][threadIdx.y + j];
}

__global__ void split_tf32_kernel(const float* __restrict__ x,
                                  float* __restrict__ hi, float* __restrict__ lo, int n)
{
    int i = blockIdx.x * 256 + threadIdx.x;
    if (i >= n) return;
    float v = x[i];
    float h = rna_tf32(v);
    hi[i] = h;
    lo[i] = v - h;
}

__global__ void round_copy_kernel(const float* __restrict__ x, float* __restrict__ y, int n4)
{
    int i = blockIdx.x * 256 + threadIdx.x;
    if (i >= n4) return;
    float4 v = ((const float4*)x)[i];
    v.x = rna_tf32(v.x); v.y = rna_tf32(v.y);
    v.z = rna_tf32(v.z); v.w = rna_tf32(v.w);
    ((float4*)y)[i] = v;
}

__global__ void gemv_kernel(const float* __restrict__ W, int ldw,
                            const float* __restrict__ x, const float* __restrict__ b,
                            float* __restrict__ y, int N, int K)
{
    int row = blockIdx.x * 8 + (threadIdx.x >> 5);
    int lane = threadIdx.x & 31;
    if (row >= N) return;
    float s = 0.0f;
    for (int k = lane; k < K; k += 32) s += W[(size_t)row * ldw + k] * x[k];
#pragma unroll
    for (int o = 16; o > 0; o >>= 1) s += __shfl_down_sync(0xFFFFFFFFu, s, o);
    if (lane == 0) y[row] = s + (b ? b[row] : 0.0f);
}

__global__ void ew_gru_kernel(const float* __restrict__ gi,
                              const float* __restrict__ gh,
                              const float* __restrict__ gated,
                              float* __restrict__ upd,
                              float* __restrict__ updr, int n)
{
    int idx = blockIdx.x * blockDim.x + threadIdx.x;
    if (idx >= n) return;
    int b = idx / MEM_DIM;
    int j = idx - b * MEM_DIM;
    size_t base = (size_t)b * NGATE;
    float r  = sigmoidf_(gi[base + j]               + gh[base + j]);
    float z  = sigmoidf_(gi[base + MEM_DIM + j]     + gh[base + MEM_DIM + j]);
    float nn = tanhf   (gi[base + 2 * MEM_DIM + j] + r * gh[base + 2 * MEM_DIM + j]);
    float u = (1.0f - z) * nn + z * gated[idx];
    upd[idx]  = u;
    updr[idx] = rna_tf32(u);
}

__global__ void fill_ones_kernel(float* __restrict__ out, int n)
{
    int idx = blockIdx.x * blockDim.x + threadIdx.x;
    if (idx < n) out[idx] = 1.0f;
}

// ---------------------------------------------------------------------------
// Launch
// ---------------------------------------------------------------------------
extern "C" void kernel_launch(void* const* d_in, const int* in_sizes, int n_in,
                              void* d_out, int out_size)
{
    const float* input      = (const float*)d_in[0];
    const float* prev       = (const float*)d_in[1];
    const float* in_proj_w  = (const float*)d_in[2];
    const float* in_proj_b  = (const float*)d_in[3];
    const float* out_proj_w = (const float*)d_in[4];
    const float* out_proj_b = (const float*)d_in[5];
    const float* ip_w       = (const float*)d_in[6];
    const float* ip_b       = (const float*)d_in[7];
    // d_in[8..9] mp_w/mp_b dead: softmax over a single key == 1
    const float* fg_w       = (const float*)d_in[10];
    const float* fg_b       = (const float*)d_in[11];
    const float* og_w       = (const float*)d_in[12];
    const float* og_b       = (const float*)d_in[13];
    const float* w_ih       = (const float*)d_in[14];
    const float* b_ih       = (const float*)d_in[15];
    const float* w_hh       = (const float*)d_in[16];
    const float* b_hh       = (const float*)d_in[17];
    float* out = (float*)d_out;

    const float* wv = in_proj_w + 2 * CTX_DIM * CTX_DIM;
    const float* bv = in_proj_b + 2 * CTX_DIM;

    float *ipT, *m1t, *m2t, *wgi, *sAh, *sAl, *sBh, *sBl, *b1, *b2, *bgi;
    float *rin, *rprev, *rfgw, *rwhh, *rogw;
    float *gi, *gh, *gated, *gatedr, *upd, *updr;
    cudaGetSymbolAddress((void**)&ipT,  g_ipT);
    cudaGetSymbolAddress((void**)&m1t,  g_m1t);
    cudaGetSymbolAddress((void**)&m2t,  g_m2t);
    cudaGetSymbolAddress((void**)&wgi,  g_wgi);
    cudaGetSymbolAddress((void**)&sAh,  g_sAh);
    cudaGetSymbolAddress((void**)&sAl,  g_sAl);
    cudaGetSymbolAddress((void**)&sBh,  g_sBh);
    cudaGetSymbolAddress((void**)&sBl,  g_sBl);
    cudaGetSymbolAddress((void**)&b1,   g_b1);
    cudaGetSymbolAddress((void**)&b2,   g_b2);
    cudaGetSymbolAddress((void**)&bgi,  g_bgi);
    cudaGetSymbolAddress((void**)&rin,  g_rin);
    cudaGetSymbolAddress((void**)&rprev,g_rprev);
    cudaGetSymbolAddress((void**)&rfgw, g_rfgw);
    cudaGetSymbolAddress((void**)&rwhh, g_rwhh);
    cudaGetSymbolAddress((void**)&rogw, g_rogw);
    cudaGetSymbolAddress((void**)&gi,   g_gi);
    cudaGetSymbolAddress((void**)&gh,   g_gh);
    cudaGetSymbolAddress((void**)&gated, g_gated);
    cudaGetSymbolAddress((void**)&gatedr,g_gatedr);
    cudaGetSymbolAddress((void**)&upd,  g_upd);
    cudaGetSymbolAddress((void**)&updr, g_updr);

    cudaFuncSetAttribute(tf32_gemm, cudaFuncAttributeMaxDynamicSharedMemorySize, SMEM_DYN);

    const Seg Z = {nullptr, 0, nullptr, 0, 0};
    const int NSQ = CTX_DIM * CTX_DIM;

    // ---- bias folds (fp32 GEMV) ----
    gemv_kernel<<<CTX_DIM / 8, 256>>>(wv,         CTX_DIM, ip_b, bv,         b1,  CTX_DIM, CTX_DIM);
    gemv_kernel<<<CTX_DIM / 8, 256>>>(out_proj_w, CTX_DIM, b1,   out_proj_b, b2,  CTX_DIM, CTX_DIM);
    gemv_kernel<<<NGATE   / 8, 256>>>(w_ih,       CTX_DIM, b2,   b_ih,       bgi, NGATE,   CTX_DIM);

    // ---- RNA-rounded operand copies (kills tf32 truncation bias) ----
    round_copy_kernel<<<(BB * IN_DIM)  / 1024, 256>>>(input, rin,  (BB * IN_DIM)  / 4);
    round_copy_kernel<<<(BB * MEM_DIM) / 1024, 256>>>(prev,  rprev,(BB * MEM_DIM) / 4);
    round_copy_kernel<<<(MEM_DIM * (MEM_DIM + IN_DIM)) / 1024, 256>>>(fg_w, rfgw, (MEM_DIM * (MEM_DIM + IN_DIM)) / 4);
    round_copy_kernel<<<(NGATE * MEM_DIM) / 1024, 256>>>(w_hh, rwhh, (NGATE * MEM_DIM) / 4);
    round_copy_kernel<<<(MEM_DIM * MEM_DIM) / 1024, 256>>>(og_w, rogw, (MEM_DIM * MEM_DIM) / 4);

    // ---- weight folds, 3-pass hi/lo compensation ----
    // M1T[IN,CTX] = ip_w^T @ wv^T
    transpose_kernel<<<dim3(IN_DIM / 32, CTX_DIM / 32), dim3(32, 8)>>>(ip_w, ipT, CTX_DIM, IN_DIM);
    split_tf32_kernel<<<NSQ / 256, 256>>>(ipT, sAh, sAl, NSQ);
    split_tf32_kernel<<<NSQ / 256, 256>>>(wv,  sBh, sBl, NSQ);
    {
        Seg a = {sAh, CTX_DIM, sBh, CTX_DIM, CTX_DIM};
        Seg b = {sAh, CTX_DIM, sBl, CTX_DIM, CTX_DIM};
        Seg c = {sAl, CTX_DIM, sBh, CTX_DIM, CTX_DIM};
        tf32_gemm<<<dim3(CTX_DIM / BN, IN_DIM / BM), 256, SMEM_DYN>>>(
            a, b, c, nullptr, nullptr, m1t, nullptr, CTX_DIM, 0, 0);
    }
    // M2T[IN,CTX] = M1T @ out_proj_w^T
    split_tf32_kernel<<<NSQ / 256, 256>>>(m1t,        sAh, sAl, NSQ);
    split_tf32_kernel<<<NSQ / 256, 256>>>(out_proj_w, sBh, sBl, NSQ);
    {
        Seg a = {sAh, CTX_DIM, sBh, CTX_DIM, CTX_DIM};
        Seg b = {sAh, CTX_DIM, sBl, CTX_DIM, CTX_DIM};
        Seg c = {sAl, CTX_DIM, sBh, CTX_DIM, CTX_DIM};
        tf32_gemm<<<dim3(CTX_DIM / BN, IN_DIM / BM), 256, SMEM_DYN>>>(
            a, b, c, nullptr, nullptr, m2t, nullptr, CTX_DIM, 0, 0);
    }
    // WGI[NGATE,IN] = w_ih @ M2T^T  (output rounded to tf32 for single-pass GI)
    split_tf32_kernel<<<(NGATE * CTX_DIM) / 256, 256>>>(w_ih, sAh, sAl, NGATE * CTX_DIM);
    split_tf32_kernel<<<NSQ / 256, 256>>>(m2t, sBh, sBl, NSQ);
    {
        Seg a = {sAh, CTX_DIM, sBh, CTX_DIM, CTX_DIM};
        Seg b = {sAh, CTX_DIM, sBl, CTX_DIM, CTX_DIM};
        Seg c = {sAl, CTX_DIM, sBh, CTX_DIM, CTX_DIM};
        tf32_gemm<<<dim3(IN_DIM / BN, NGATE / BM), 256, SMEM_DYN>>>(
            a, b, c, nullptr, nullptr, wgi, nullptr, IN_DIM, 0, 1);
    }

    // ---- GI = input @ WGI^T + bgi ----
    {
        Seg a = {rin, IN_DIM, wgi, IN_DIM, IN_DIM};
        tf32_gemm<<<dim3(NGATE / BN, BB / BM), 256, SMEM_DYN>>>(
            a, Z, Z, bgi, nullptr, gi, nullptr, NGATE, 0, 0);
    }
    // ---- forget gate fused: gated = prev * sigmoid(prev@fgA^T + input@fgB^T + fg_b) ----
    {
        Seg a = {rprev, MEM_DIM, rfgw,           MEM_DIM + IN_DIM, MEM_DIM};
        Seg b = {rin,   IN_DIM,  rfgw + MEM_DIM, MEM_DIM + IN_DIM, IN_DIM};
        tf32_gemm<<<dim3(MEM_DIM / BN, BB / BM), 256, SMEM_DYN>>>(
            a, b, Z, fg_b, prev, gated, gatedr, MEM_DIM, 2, 0);
    }
    // ---- GH = gated @ w_hh^T + b_hh ----
    {
        Seg a = {gatedr, MEM_DIM, rwhh, MEM_DIM, MEM_DIM};
        tf32_gemm<<<dim3(NGATE / BN, BB / BM), 256, SMEM_DYN>>>(
            a, Z, Z, b_hh, nullptr, gh, nullptr, NGATE, 0, 0);
    }
    // ---- GRU elementwise (writes exact + rounded upd) ----
    ew_gru_kernel<<<(BB * MEM_DIM) / 256, 256>>>(gi, gh, gated, upd, updr, BB * MEM_DIM);
    // ---- output gate fused: out = upd * sigmoid(upd@og_w^T + og_b) ----
    {
        Seg a = {updr, MEM_DIM, rogw, MEM_DIM, MEM_DIM};
        tf32_gemm<<<dim3(MEM_DIM / BN, BB / BM), 256, SMEM_DYN>>>(
            a, Z, Z, og_b, upd, out, nullptr, MEM_DIM, 1, 0);
    }
    // ---- attention weights: softmax over single key == 1.0 ----
    int tail = out_size - BB * MEM_DIM;
    if (tail > 0)
        fill_ones_kernel<<<(tail + 255) / 256, 256>>>(out + BB * MEM_DIM, tail);
}

// round 5
// speedup vs baseline: 3.0790x; 1.1510x over previous
#include <cuda_runtime.h>
#include <math.h>
#include <stdint.h>

#define BB      8192
#define IN_DIM  1024
#define MEM_DIM 1024
#define CTX_DIM 1024
#define NGATE   3072

// ---- GEMM tiling ----
#define BM 128
#define BN 128
#define BK 32
#define PAD 36                    // floats per smem row (16B-aligned, conflict-free frags)
#define STG 3
#define TILE_F (BM * PAD)
#define STAGE_F (2 * TILE_F)
#define SMEM_DYN (STG * STAGE_F * 4)   // 110592 bytes

#define ZSPLIT 4

// ---------------------------------------------------------------------------
// Device scratch (__device__ globals; allocation-free rule)
// ---------------------------------------------------------------------------
__device__ __align__(256) float g_ipT [IN_DIM * CTX_DIM];
__device__ __align__(256) float g_m1t [IN_DIM * CTX_DIM];
__device__ __align__(256) float g_m2t [IN_DIM * CTX_DIM];
__device__ __align__(256) float g_wgi [NGATE  * IN_DIM];
__device__ __align__(256) float g_sAh [NGATE  * CTX_DIM];
__device__ __align__(256) float g_sAl [NGATE  * CTX_DIM];
__device__ __align__(256) float g_sBh [CTX_DIM * CTX_DIM];
__device__ __align__(256) float g_sBl [CTX_DIM * CTX_DIM];
__device__ __align__(256) float g_part[ZSPLIT * NGATE * IN_DIM];
__device__ __align__(256) float g_b1  [CTX_DIM];
__device__ __align__(256) float g_b2  [CTX_DIM];
__device__ __align__(256) float g_bgi [NGATE];
__device__ __align__(256) float g_rfgw[MEM_DIM * (MEM_DIM + IN_DIM)];
__device__ __align__(256) float g_rwhh[NGATE * MEM_DIM];
__device__ __align__(256) float g_rogw[MEM_DIM * MEM_DIM];
__device__ __align__(256) float g_gi  [(size_t)BB * NGATE];
__device__ __align__(256) float g_gh  [(size_t)BB * NGATE];
__device__ __align__(256) float g_gated[(size_t)BB * MEM_DIM];
__device__ __align__(256) float g_upd [(size_t)BB * MEM_DIM];

// ---------------------------------------------------------------------------
// Helpers
// ---------------------------------------------------------------------------
__device__ __forceinline__ float sigmoidf_(float x) { return 1.0f / (1.0f + expf(-x)); }
__device__ __forceinline__ float rna_tf32(float x) {
    uint32_t u;
    asm("cvt.rna.tf32.f32 %0, %1;" : "=r"(u) : "f"(x));
    return __uint_as_float(u);
}

// ---------------------------------------------------------------------------
// Segmented tf32 mma.sync GEMM with optional split-K (blockIdx.z) and
// in-register rna rounding of A fragments (RA=1).
//   pre[m,n] = sum_seg sum_k A_seg[m,k]*B_seg[n,k]  (+bias[n])
//   mode 0: C = pre      mode 1: C = mul * sigmoid(pre)
// A_seg [M,K] row-major, B_seg [N,K] row-major. M,N mult of 128, K_seg mult of 32.
// With gridDim.z = Z > 1: slice z computes iters [z*niter/Z,(z+1)*niter/Z) and
// writes to C + z*partM*ldc (bias/mul must be null, mode 0).
// ---------------------------------------------------------------------------
struct Seg { const float* A; int lda; const float* B; int ldb; int K; };

template <int RA>
__global__ __launch_bounds__(256, 2)
void tf32_gemm(Seg s0, Seg s1, Seg s2,
               const float* __restrict__ bias,
               const float* __restrict__ mul,
               float* __restrict__ C,
               int ldc, int mode, int partM)
{
    extern __shared__ float smf[];
    uint32_t sbase;
    asm("{ .reg .u64 t; cvta.to.shared.u64 t, %1; cvt.u32.u64 %0, t; }"
        : "=r"(sbase) : "l"(smf));

    const int tid = threadIdx.x;
    const int wid = tid >> 5, lid = tid & 31;
    const int g = lid >> 2, tg = lid & 3;
    const int wm = wid & 3, wn = wid >> 2;          // warp grid 4(M) x 2(N)
    const int row0 = blockIdx.y * BM, col0 = blockIdx.x * BN;

    const int e0 = s0.K / BK;
    const int e1 = e0 + s1.K / BK;
    const int niter_tot = e1 + s2.K / BK;
    const int cnt = niter_tot / gridDim.z;
    const int it0 = blockIdx.z * cnt;
    const int it1 = it0 + cnt;

    C += (size_t)blockIdx.z * partM * ldc;

    const float* A0 = s0.A + (size_t)row0 * s0.lda;
    const float* B0 = s0.B + (size_t)col0 * s0.ldb;
    const float* A1 = s1.A ? s1.A + (size_t)row0 * s1.lda : A0;
    const float* B1 = s1.B ? s1.B + (size_t)col0 * s1.ldb : B0;
    const float* A2 = s2.A ? s2.A + (size_t)row0 * s2.lda : A0;
    const float* B2 = s2.B ? s2.B + (size_t)col0 * s2.ldb : B0;

    auto load_stage = [&](int s, int kc) {
        const float* Ag; const float* Bg; int lda, ldb, k0;
        if (kc < e0)      { Ag = A0; Bg = B0; lda = s0.lda; ldb = s0.ldb; k0 = kc * BK; }
        else if (kc < e1) { Ag = A1; Bg = B1; lda = s1.lda; ldb = s1.ldb; k0 = (kc - e0) * BK; }
        else              { Ag = A2; Bg = B2; lda = s2.lda; ldb = s2.ldb; k0 = (kc - e1) * BK; }
        const uint32_t sa = sbase + (uint32_t)s * STAGE_F * 4;
        const uint32_t sb = sa + TILE_F * 4;
#pragma unroll
        for (int i = 0; i < 4; i++) {
            int c = tid + i * 256, r = c >> 3, ch = c & 7;
            asm volatile("cp.async.cg.shared.global [%0], [%1], 16;"
                :: "r"(sa + (uint32_t)(r * PAD + ch * 4) * 4),
                   "l"(Ag + (size_t)r * lda + k0 + ch * 4) : "memory");
        }
#pragma unroll
        for (int i = 0; i < 4; i++) {
            int c = tid + i * 256, r = c >> 3, ch = c & 7;
            asm volatile("cp.async.cg.shared.global [%0], [%1], 16;"
                :: "r"(sb + (uint32_t)(r * PAD + ch * 4) * 4),
                   "l"(Bg + (size_t)r * ldb + k0 + ch * 4) : "memory");
        }
    };

    float acc[2][8][4];
#pragma unroll
    for (int mt = 0; mt < 2; mt++)
#pragma unroll
        for (int nt = 0; nt < 8; nt++)
#pragma unroll
            for (int e = 0; e < 4; e++) acc[mt][nt][e] = 0.0f;

    for (int p = 0; p < STG - 1; p++) {
        load_stage(p, it0 + p);
        asm volatile("cp.async.commit_group;" ::: "memory");
    }

    for (int it = it0; it < it1; it++) {
        const int pre = it + STG - 1;
        if (pre < it1) load_stage((pre - it0) % STG, pre);
        asm volatile("cp.async.commit_group;" ::: "memory");
        asm volatile("cp.async.wait_group %0;" :: "n"(STG - 1) : "memory");
        __syncthreads();

        const float* As = smf + ((it - it0) % STG) * STAGE_F;
        const float* Bs = As + TILE_F;
#pragma unroll
        for (int kk = 0; kk < 4; kk++) {
            const int k = kk * 8;
            uint32_t af[2][4], bf[8][2];
#pragma unroll
            for (int mt = 0; mt < 2; mt++) {
                const float* ap = As + (wm * 32 + mt * 16 + g) * PAD + k + tg;
                float f0 = ap[0], f1 = ap[8 * PAD], f2 = ap[4], f3 = ap[8 * PAD + 4];
                if (RA) { f0 = rna_tf32(f0); f1 = rna_tf32(f1);
                          f2 = rna_tf32(f2); f3 = rna_tf32(f3); }
                af[mt][0] = __float_as_uint(f0);
                af[mt][1] = __float_as_uint(f1);
                af[mt][2] = __float_as_uint(f2);
                af[mt][3] = __float_as_uint(f3);
            }
#pragma unroll
            for (int nt = 0; nt < 8; nt++) {
                const float* bp = Bs + (wn * 64 + nt * 8 + g) * PAD + k + tg;
                bf[nt][0] = __float_as_uint(bp[0]);
                bf[nt][1] = __float_as_uint(bp[4]);
            }
#pragma unroll
            for (int mt = 0; mt < 2; mt++)
#pragma unroll
                for (int nt = 0; nt < 8; nt++)
                    asm volatile(
                        "mma.sync.aligned.m16n8k8.row.col.f32.tf32.tf32.f32 "
                        "{%0,%1,%2,%3}, {%4,%5,%6,%7}, {%8,%9}, {%0,%1,%2,%3};"
                        : "+f"(acc[mt][nt][0]), "+f"(acc[mt][nt][1]),
                          "+f"(acc[mt][nt][2]), "+f"(acc[mt][nt][3])
                        : "r"(af[mt][0]), "r"(af[mt][1]), "r"(af[mt][2]), "r"(af[mt][3]),
                          "r"(bf[nt][0]), "r"(bf[nt][1]));
        }
        __syncthreads();
    }

    // ---- epilogue ----
#pragma unroll
    for (int mt = 0; mt < 2; mt++)
#pragma unroll
        for (int h = 0; h < 2; h++) {
            const int row = row0 + wm * 32 + mt * 16 + g + h * 8;
            float* crow       = C + (size_t)row * ldc + col0 + wn * 64;
            const float* mrow = mul ? mul + (size_t)row * ldc + col0 + wn * 64 : nullptr;
#pragma unroll
            for (int nt = 0; nt < 8; nt++) {
                const int col = nt * 8 + 2 * tg;
                float v0 = acc[mt][nt][h * 2 + 0];
                float v1 = acc[mt][nt][h * 2 + 1];
                if (bias) {
                    v0 += bias[col0 + wn * 64 + col];
                    v1 += bias[col0 + wn * 64 + col + 1];
                }
                if (mode == 1) {
                    float2 m = *(const float2*)(mrow + col);
                    v0 = m.x * sigmoidf_(v0);
                    v1 = m.y * sigmoidf_(v1);
                }
                *(float2*)(crow + col) = make_float2(v0, v1);
            }
        }
}

// ---------------------------------------------------------------------------
// Small kernels
// ---------------------------------------------------------------------------
__global__ void transpose_kernel(const float* __restrict__ src, float* __restrict__ dst,
                                 int R, int C)
{
    __shared__ float t[32][33];
    int bx = blockIdx.x * 32, by = blockIdx.y * 32;
#pragma unroll
    for (int j = 0; j < 32; j += 8)
        t[threadIdx.y + j][threadIdx.x] = src[(size_t)(by + threadIdx.y + j) * C + bx + threadIdx.x];
    __syncthreads();
#pragma unroll
    for (int j = 0; j < 32; j += 8)
        dst[(size_t)(bx + threadIdx.y + j) * R + by + threadIdx.x] = t[threadIdx.x][threadIdx.y + j];
}

__global__ void split_tf32_kernel(const float* __restrict__ x,
                                  float* __restrict__ hi, float* __restrict__ lo, int n)
{
    int i = blockIdx.x * 256 + threadIdx.x;
    if (i >= n) return;
    float v = x[i];
    float h = rna_tf32(v);
    hi[i] = h;
    lo[i] = v - h;
}

__global__ void round_copy_kernel(const float* __restrict__ x, float* __restrict__ y, int n4)
{
    int i = blockIdx.x * 256 + threadIdx.x;
    if (i >= n4) return;
    float4 v = ((const float4*)x)[i];
    v.x = rna_tf32(v.x); v.y = rna_tf32(v.y);
    v.z = rna_tf32(v.z); v.w = rna_tf32(v.w);
    ((float4*)y)[i] = v;
}

// dst[i] = (round?) sum_z part[i + z*stride]   (deterministic order)
__global__ void reduce_z_kernel(const float* __restrict__ part, float* __restrict__ dst,
                                int n4, int Z, int strideF, int do_round)
{
    int i = blockIdx.x * 256 + threadIdx.x;
    if (i >= n4) return;
    const float4* p = (const float4*)part;
    int s4 = strideF / 4;
    float4 a = p[i];
    for (int z = 1; z < Z; z++) {
        float4 v = p[i + z * s4];
        a.x += v.x; a.y += v.y; a.z += v.z; a.w += v.w;
    }
    if (do_round) {
        a.x = rna_tf32(a.x); a.y = rna_tf32(a.y);
        a.z = rna_tf32(a.z); a.w = rna_tf32(a.w);
    }
    ((float4*)dst)[i] = a;
}

__global__ void gemv_kernel(const float* __restrict__ W, int ldw,
                            const float* __restrict__ x, const float* __restrict__ b,
                            float* __restrict__ y, int N, int K)
{
    int row = blockIdx.x * 8 + (threadIdx.x >> 5);
    int lane = threadIdx.x & 31;
    if (row >= N) return;
    float s = 0.0f;
    for (int k = lane; k < K; k += 32) s += W[(size_t)row * ldw + k] * x[k];
#pragma unroll
    for (int o = 16; o > 0; o >>= 1) s += __shfl_down_sync(0xFFFFFFFFu, s, o);
    if (lane == 0) y[row] = s + (b ? b[row] : 0.0f);
}

__global__ void ew_gru_kernel(const float4* __restrict__ gi,
                              const float4* __restrict__ gh,
                              const float4* __restrict__ gated,
                              float4* __restrict__ upd, int n4)
{
    int i = blockIdx.x * 256 + threadIdx.x;
    if (i >= n4) return;
    const int M4 = MEM_DIM / 4;
    int b = i / M4, j = i - b * M4;
    size_t base = (size_t)b * (NGATE / 4);
    float4 gir = gi[base + j],          ghr = gh[base + j];
    float4 giz = gi[base + M4 + j],     ghz = gh[base + M4 + j];
    float4 gin = gi[base + 2 * M4 + j], ghn = gh[base + 2 * M4 + j];
    float4 gd = gated[i];
    float4 u;
    {
        float r = sigmoidf_(gir.x + ghr.x), z = sigmoidf_(giz.x + ghz.x);
        float nn = tanhf(gin.x + r * ghn.x);
        u.x = (1.0f - z) * nn + z * gd.x;
    }
    {
        float r = sigmoidf_(gir.y + ghr.y), z = sigmoidf_(giz.y + ghz.y);
        float nn = tanhf(gin.y + r * ghn.y);
        u.y = (1.0f - z) * nn + z * gd.y;
    }
    {
        float r = sigmoidf_(gir.z + ghr.z), z = sigmoidf_(giz.z + ghz.z);
        float nn = tanhf(gin.z + r * ghn.z);
        u.z = (1.0f - z) * nn + z * gd.z;
    }
    {
        float r = sigmoidf_(gir.w + ghr.w), z = sigmoidf_(giz.w + ghz.w);
        float nn = tanhf(gin.w + r * ghn.w);
        u.w = (1.0f - z) * nn + z * gd.w;
    }
    upd[i] = u;
}

__global__ void fill_ones_kernel(float* __restrict__ out, int n)
{
    int idx = blockIdx.x * blockDim.x + threadIdx.x;
    if (idx < n) out[idx] = 1.0f;
}

// ---------------------------------------------------------------------------
// Launch
// ---------------------------------------------------------------------------
extern "C" void kernel_launch(void* const* d_in, const int* in_sizes, int n_in,
                              void* d_out, int out_size)
{
    const float* input      = (const float*)d_in[0];
    const float* prev       = (const float*)d_in[1];
    const float* in_proj_w  = (const float*)d_in[2];
    const float* in_proj_b  = (const float*)d_in[3];
    const float* out_proj_w = (const float*)d_in[4];
    const float* out_proj_b = (const float*)d_in[5];
    const float* ip_w       = (const float*)d_in[6];
    const float* ip_b       = (const float*)d_in[7];
    // d_in[8..9] mp_w/mp_b dead: softmax over a single key == 1
    const float* fg_w       = (const float*)d_in[10];
    const float* fg_b       = (const float*)d_in[11];
    const float* og_w       = (const float*)d_in[12];
    const float* og_b       = (const float*)d_in[13];
    const float* w_ih       = (const float*)d_in[14];
    const float* b_ih       = (const float*)d_in[15];
    const float* w_hh       = (const float*)d_in[16];
    const float* b_hh       = (const float*)d_in[17];
    float* out = (float*)d_out;

    const float* wv = in_proj_w + 2 * CTX_DIM * CTX_DIM;
    const float* bv = in_proj_b + 2 * CTX_DIM;

    float *ipT, *m1t, *m2t, *wgi, *sAh, *sAl, *sBh, *sBl, *part;
    float *b1, *b2, *bgi, *rfgw, *rwhh, *rogw, *gi, *gh, *gated, *upd;
    cudaGetSymbolAddress((void**)&ipT,  g_ipT);
    cudaGetSymbolAddress((void**)&m1t,  g_m1t);
    cudaGetSymbolAddress((void**)&m2t,  g_m2t);
    cudaGetSymbolAddress((void**)&wgi,  g_wgi);
    cudaGetSymbolAddress((void**)&sAh,  g_sAh);
    cudaGetSymbolAddress((void**)&sAl,  g_sAl);
    cudaGetSymbolAddress((void**)&sBh,  g_sBh);
    cudaGetSymbolAddress((void**)&sBl,  g_sBl);
    cudaGetSymbolAddress((void**)&part, g_part);
    cudaGetSymbolAddress((void**)&b1,   g_b1);
    cudaGetSymbolAddress((void**)&b2,   g_b2);
    cudaGetSymbolAddress((void**)&bgi,  g_bgi);
    cudaGetSymbolAddress((void**)&rfgw, g_rfgw);
    cudaGetSymbolAddress((void**)&rwhh, g_rwhh);
    cudaGetSymbolAddress((void**)&rogw, g_rogw);
    cudaGetSymbolAddress((void**)&gi,   g_gi);
    cudaGetSymbolAddress((void**)&gh,   g_gh);
    cudaGetSymbolAddress((void**)&gated, g_gated);
    cudaGetSymbolAddress((void**)&upd,  g_upd);

    cudaFuncSetAttribute(tf32_gemm<0>, cudaFuncAttributeMaxDynamicSharedMemorySize, SMEM_DYN);
    cudaFuncSetAttribute(tf32_gemm<1>, cudaFuncAttributeMaxDynamicSharedMemorySize, SMEM_DYN);

    const Seg Z = {nullptr, 0, nullptr, 0, 0};
    const int NSQ = CTX_DIM * CTX_DIM;

    // #0-2: bias folds (fp32 GEMV)
    gemv_kernel<<<CTX_DIM / 8, 256>>>(wv,         CTX_DIM, ip_b, bv,         b1,  CTX_DIM, CTX_DIM);
    gemv_kernel<<<CTX_DIM / 8, 256>>>(out_proj_w, CTX_DIM, b1,   out_proj_b, b2,  CTX_DIM, CTX_DIM);
    gemv_kernel<<<NGATE   / 8, 256>>>(w_ih,       CTX_DIM, b2,   b_ih,       bgi, NGATE,   CTX_DIM);

    // #3-4: rounded weight copies needed by FG/GH
    round_copy_kernel<<<(MEM_DIM * (MEM_DIM + IN_DIM)) / 1024, 256>>>(
        fg_w, rfgw, (MEM_DIM * (MEM_DIM + IN_DIM)) / 4);
    round_copy_kernel<<<(NGATE * MEM_DIM) / 1024, 256>>>(w_hh, rwhh, (NGATE * MEM_DIM) / 4);

    // #5: FG GEMM (ncu profiles launch index 5): gated = prev * sigmoid(...)
    {
        Seg a = {prev,  MEM_DIM, rfgw,           MEM_DIM + IN_DIM, MEM_DIM};
        Seg b = {input, IN_DIM,  rfgw + MEM_DIM, MEM_DIM + IN_DIM, IN_DIM};
        tf32_gemm<1><<<dim3(MEM_DIM / BN, BB / BM), 256, SMEM_DYN>>>(
            a, b, Z, fg_b, prev, gated, MEM_DIM, 1, 0);
    }
    // #6: GH = gated @ w_hh^T + b_hh
    {
        Seg a = {gated, MEM_DIM, rwhh, MEM_DIM, MEM_DIM};
        tf32_gemm<1><<<dim3(NGATE / BN, BB / BM), 256, SMEM_DYN>>>(
            a, Z, Z, b_hh, nullptr, gh, NGATE, 0, 0);
    }
    // #7: rounded og_w
    round_copy_kernel<<<(MEM_DIM * MEM_DIM) / 1024, 256>>>(og_w, rogw, (MEM_DIM * MEM_DIM) / 4);

    // ---- weight folds, 3-pass hi/lo compensation, split-K Z=4 ----
    transpose_kernel<<<dim3(IN_DIM / 32, CTX_DIM / 32), dim3(32, 8)>>>(ip_w, ipT, CTX_DIM, IN_DIM);
    split_tf32_kernel<<<NSQ / 256, 256>>>(ipT, sAh, sAl, NSQ);
    split_tf32_kernel<<<NSQ / 256, 256>>>(wv,  sBh, sBl, NSQ);
    {   // M1T[IN,CTX] = ip_w^T @ wv^T
        Seg a = {sAh, CTX_DIM, sBh, CTX_DIM, CTX_DIM};
        Seg b = {sAh, CTX_DIM, sBl, CTX_DIM, CTX_DIM};
        Seg c = {sAl, CTX_DIM, sBh, CTX_DIM, CTX_DIM};
        tf32_gemm<0><<<dim3(CTX_DIM / BN, IN_DIM / BM, ZSPLIT), 256, SMEM_DYN>>>(
            a, b, c, nullptr, nullptr, part, CTX_DIM, 0, IN_DIM);
        reduce_z_kernel<<<NSQ / 1024, 256>>>(part, m1t, NSQ / 4, ZSPLIT, NSQ, 0);
    }
    split_tf32_kernel<<<NSQ / 256, 256>>>(m1t,        sAh, sAl, NSQ);
    split_tf32_kernel<<<NSQ / 256, 256>>>(out_proj_w, sBh, sBl, NSQ);
    {   // M2T[IN,CTX] = M1T @ out_proj_w^T
        Seg a = {sAh, CTX_DIM, sBh, CTX_DIM, CTX_DIM};
        Seg b = {sAh, CTX_DIM, sBl, CTX_DIM, CTX_DIM};
        Seg c = {sAl, CTX_DIM, sBh, CTX_DIM, CTX_DIM};
        tf32_gemm<0><<<dim3(CTX_DIM / BN, IN_DIM / BM, ZSPLIT), 256, SMEM_DYN>>>(
            a, b, c, nullptr, nullptr, part, CTX_DIM, 0, IN_DIM);
        reduce_z_kernel<<<NSQ / 1024, 256>>>(part, m2t, NSQ / 4, ZSPLIT, NSQ, 0);
    }
    split_tf32_kernel<<<(NGATE * CTX_DIM) / 256, 256>>>(w_ih, sAh, sAl, NGATE * CTX_DIM);
    split_tf32_kernel<<<NSQ / 256, 256>>>(m2t, sBh, sBl, NSQ);
    {   // WGI[NGATE,IN] = w_ih @ M2T^T  (reduce rounds output to tf32)
        Seg a = {sAh, CTX_DIM, sBh, CTX_DIM, CTX_DIM};
        Seg b = {sAh, CTX_DIM, sBl, CTX_DIM, CTX_DIM};
        Seg c = {sAl, CTX_DIM, sBh, CTX_DIM, CTX_DIM};
        tf32_gemm<0><<<dim3(IN_DIM / BN, NGATE / BM, ZSPLIT), 256, SMEM_DYN>>>(
            a, b, c, nullptr, nullptr, part, IN_DIM, 0, NGATE);
        reduce_z_kernel<<<(NGATE * IN_DIM) / 1024, 256>>>(
            part, wgi, (NGATE * IN_DIM) / 4, ZSPLIT, NGATE * IN_DIM, 1);
    }

    // GI = input @ WGI^T + bgi
    {
        Seg a = {input, IN_DIM, wgi, IN_DIM, IN_DIM};
        tf32_gemm<1><<<dim3(NGATE / BN, BB / BM), 256, SMEM_DYN>>>(
            a, Z, Z, bgi, nullptr, gi, NGATE, 0, 0);
    }
    // GRU elementwise
    ew_gru_kernel<<<(BB * MEM_DIM / 4 + 255) / 256, 256>>>(
        (const float4*)gi, (const float4*)gh, (const float4*)gated,
        (float4*)upd, BB * MEM_DIM / 4);
    // out = upd * sigmoid(upd @ og_w^T + og_b)
    {
        Seg a = {upd, MEM_DIM, rogw, MEM_DIM, MEM_DIM};
        tf32_gemm<1><<<dim3(MEM_DIM / BN, BB / BM), 256, SMEM_DYN>>>(
            a, Z, Z, og_b, upd, out, MEM_DIM, 1, 0);
    }
    // attention weights: softmax over single key == 1.0
    int tail = out_size - BB * MEM_DIM;
    if (tail > 0)
        fill_ones_kernel<<<(tail + 255) / 256, 256>>>(out + BB * MEM_DIM, tail);
}

// round 6
// speedup vs baseline: 4.8362x; 1.5707x over previous
#include <cuda_runtime.h>
#include <cuda_fp16.h>
#include <math.h>
#include <stdint.h>

#define BB      8192
#define IN_DIM  1024
#define MEM_DIM 1024
#define CTX_DIM 1024
#define NGATE   3072

// ---- fp16 GEMM tiling ----
#define BM 128
#define BN 128
#define BK 32
#define LDH 40                     // halfs per smem row (80B; conflict-free)
#define STG 4
#define TILE_H (BM * LDH)          // 5120 halfs
#define STAGE_B (2 * TILE_H * 2)   // 20480 bytes
#define SMEM_DYN (STG * STAGE_B)   // 81920 bytes

#define ZSPLIT 4

// ---------------------------------------------------------------------------
// Device scratch
// ---------------------------------------------------------------------------
__device__ __align__(256) float  g_ipT [IN_DIM * CTX_DIM];
__device__ __align__(256) float  g_m1t [IN_DIM * CTX_DIM];
__device__ __align__(256) float  g_m2t [IN_DIM * CTX_DIM];
__device__ __align__(256) float  g_part[ZSPLIT * NGATE * IN_DIM];
__device__ __align__(256) float  g_b1  [CTX_DIM];
__device__ __align__(256) float  g_b2  [CTX_DIM];
__device__ __align__(256) float  g_bgi [NGATE];
__device__ __align__(256) float  g_gi  [(size_t)BB * NGATE];
__device__ __align__(256) float  g_gh  [(size_t)BB * NGATE];
__device__ __align__(256) float  g_gated[(size_t)BB * MEM_DIM];
__device__ __align__(256) float  g_upd [(size_t)BB * MEM_DIM];
// fp16 operands
__device__ __align__(256) __half g_inh [(size_t)BB * IN_DIM];
__device__ __align__(256) __half g_pvh [(size_t)BB * MEM_DIM];
__device__ __align__(256) __half g_fgwh[MEM_DIM * (MEM_DIM + IN_DIM)];
__device__ __align__(256) __half g_whhh[NGATE * MEM_DIM];
__device__ __align__(256) __half g_ogwh[MEM_DIM * MEM_DIM];
__device__ __align__(256) __half g_wgih[NGATE * IN_DIM];
__device__ __align__(256) __half g_gth [(size_t)BB * MEM_DIM];
__device__ __align__(256) __half g_udh [(size_t)BB * MEM_DIM];
__device__ __align__(256) __half g_sAh [NGATE * CTX_DIM];
__device__ __align__(256) __half g_sAl [NGATE * CTX_DIM];
__device__ __align__(256) __half g_sBh [CTX_DIM * CTX_DIM];
__device__ __align__(256) __half g_sBl [CTX_DIM * CTX_DIM];

// ---------------------------------------------------------------------------
// Helpers
// ---------------------------------------------------------------------------
__device__ __forceinline__ float sigmoidf_(float x) { return 1.0f / (1.0f + expf(-x)); }
__device__ __forceinline__ uint32_t pack2h(float a, float b) {
    __half2 h = __float22half2_rn(make_float2(a, b));
    return *(uint32_t*)&h;
}

// ---------------------------------------------------------------------------
// Segmented fp16 mma.sync GEMM (f32 accumulate), optional split-K.
//   pre[m,n] = sum_seg sum_k A_seg[m,k]*B_seg[n,k]  (+bias[n])
//   mode 0: C = pre      mode 1: C = mul * sigmoid(pre)
//   C2 (half, optional): half copy of C.
// A_seg [M,K] row-major halfs, B_seg [N,K] row-major halfs.
// gridDim.z = Z > 1: slice z does iters [z*n/Z,(z+1)*n/Z), C += z*partM*ldc.
// ---------------------------------------------------------------------------
struct Seg { const __half* A; int lda; const __half* B; int ldb; int K; };

__global__ __launch_bounds__(256, 2)
void h16_gemm(Seg s0, Seg s1, Seg s2,
              const float* __restrict__ bias,
              const float* __restrict__ mul,
              float* __restrict__ C, __half* __restrict__ C2,
              int ldc, int mode, int partM)
{
    extern __shared__ __half smh[];
    uint32_t sbase;
    asm("{ .reg .u64 t; cvta.to.shared.u64 t, %1; cvt.u32.u64 %0, t; }"
        : "=r"(sbase) : "l"(smh));

    const int tid = threadIdx.x;
    const int wid = tid >> 5, lid = tid & 31;
    const int g = lid >> 2, tg = lid & 3;
    const int wm = wid & 3, wn = wid >> 2;          // warps: 4(M) x 2(N)
    const int row0 = blockIdx.y * BM, col0 = blockIdx.x * BN;

    const int e0 = s0.K / BK;
    const int e1 = e0 + s1.K / BK;
    const int niter_tot = e1 + s2.K / BK;
    const int cnt = niter_tot / gridDim.z;
    const int it0 = blockIdx.z * cnt;
    const int it1 = it0 + cnt;

    C += (size_t)blockIdx.z * partM * ldc;

    const __half* A0 = s0.A + (size_t)row0 * s0.lda;
    const __half* B0 = s0.B + (size_t)col0 * s0.ldb;
    const __half* A1 = s1.A ? s1.A + (size_t)row0 * s1.lda : A0;
    const __half* B1 = s1.B ? s1.B + (size_t)col0 * s1.ldb : B0;
    const __half* A2 = s2.A ? s2.A + (size_t)row0 * s2.lda : A0;
    const __half* B2 = s2.B ? s2.B + (size_t)col0 * s2.ldb : B0;

    auto load_stage = [&](int s, int kc) {
        const __half* Ag; const __half* Bg; int lda, ldb, k0;
        if (kc < e0)      { Ag = A0; Bg = B0; lda = s0.lda; ldb = s0.ldb; k0 = kc * BK; }
        else if (kc < e1) { Ag = A1; Bg = B1; lda = s1.lda; ldb = s1.ldb; k0 = (kc - e0) * BK; }
        else              { Ag = A2; Bg = B2; lda = s2.lda; ldb = s2.ldb; k0 = (kc - e1) * BK; }
        const uint32_t sa = sbase + (uint32_t)s * STAGE_B;
        const uint32_t sb = sa + TILE_H * 2;
#pragma unroll
        for (int i = 0; i < 2; i++) {
            int c = tid + i * 256, r = c >> 2, ch = c & 3;
            asm volatile("cp.async.cg.shared.global [%0], [%1], 16;"
                :: "r"(sa + (uint32_t)(r * 80 + ch * 16)),
                   "l"(Ag + (size_t)r * lda + k0 + ch * 8) : "memory");
        }
#pragma unroll
        for (int i = 0; i < 2; i++) {
            int c = tid + i * 256, r = c >> 2, ch = c & 3;
            asm volatile("cp.async.cg.shared.global [%0], [%1], 16;"
                :: "r"(sb + (uint32_t)(r * 80 + ch * 16)),
                   "l"(Bg + (size_t)r * ldb + k0 + ch * 8) : "memory");
        }
    };

    float acc[2][8][4];
#pragma unroll
    for (int mt = 0; mt < 2; mt++)
#pragma unroll
        for (int nt = 0; nt < 8; nt++)
#pragma unroll
            for (int e = 0; e < 4; e++) acc[mt][nt][e] = 0.0f;

    for (int p = 0; p < STG - 1; p++) {
        load_stage(p, it0 + p);
        asm volatile("cp.async.commit_group;" ::: "memory");
    }

    for (int it = it0; it < it1; it++) {
        const int pre = it + STG - 1;
        if (pre < it1) load_stage((pre - it0) % STG, pre);
        asm volatile("cp.async.commit_group;" ::: "memory");
        asm volatile("cp.async.wait_group %0;" :: "n"(STG - 1) : "memory");
        __syncthreads();

        const __half* As = smh + ((it - it0) % STG) * (2 * TILE_H);
        const __half* Bs = As + TILE_H;
#pragma unroll
        for (int ks = 0; ks < 2; ks++) {
            const int kb = ks * 16;
            uint32_t af[2][4], bf[8][2];
#pragma unroll
            for (int mt = 0; mt < 2; mt++) {
                const __half* ap = As + (wm * 32 + mt * 16 + g) * LDH + kb + 2 * tg;
                af[mt][0] = *(const uint32_t*)(ap);
                af[mt][1] = *(const uint32_t*)(ap + 8 * LDH);
                af[mt][2] = *(const uint32_t*)(ap + 8);
                af[mt][3] = *(const uint32_t*)(ap + 8 * LDH + 8);
            }
#pragma unroll
            for (int nt = 0; nt < 8; nt++) {
                const __half* bp = Bs + (wn * 64 + nt * 8 + g) * LDH + kb + 2 * tg;
                bf[nt][0] = *(const uint32_t*)(bp);
                bf[nt][1] = *(const uint32_t*)(bp + 8);
            }
#pragma unroll
            for (int mt = 0; mt < 2; mt++)
#pragma unroll
                for (int nt = 0; nt < 8; nt++)
                    asm volatile(
                        "mma.sync.aligned.m16n8k16.row.col.f32.f16.f16.f32 "
                        "{%0,%1,%2,%3}, {%4,%5,%6,%7}, {%8,%9}, {%0,%1,%2,%3};"
                        : "+f"(acc[mt][nt][0]), "+f"(acc[mt][nt][1]),
                          "+f"(acc[mt][nt][2]), "+f"(acc[mt][nt][3])
                        : "r"(af[mt][0]), "r"(af[mt][1]), "r"(af[mt][2]), "r"(af[mt][3]),
                          "r"(bf[nt][0]), "r"(bf[nt][1]));
        }
        __syncthreads();
    }

    // ---- epilogue ----
#pragma unroll
    for (int mt = 0; mt < 2; mt++)
#pragma unroll
        for (int h = 0; h < 2; h++) {
            const int row = row0 + wm * 32 + mt * 16 + g + h * 8;
            float* crow        = C + (size_t)row * ldc + col0 + wn * 64;
            const float* mrow  = mul ? mul + (size_t)row * ldc + col0 + wn * 64 : nullptr;
            __half* c2row      = C2 ? C2 + (size_t)row * ldc + col0 + wn * 64 : nullptr;
#pragma unroll
            for (int nt = 0; nt < 8; nt++) {
                const int col = nt * 8 + 2 * tg;
                float v0 = acc[mt][nt][h * 2 + 0];
                float v1 = acc[mt][nt][h * 2 + 1];
                if (bias) {
                    v0 += bias[col0 + wn * 64 + col];
                    v1 += bias[col0 + wn * 64 + col + 1];
                }
                if (mode == 1) {
                    float2 m = *(const float2*)(mrow + col);
                    v0 = m.x * sigmoidf_(v0);
                    v1 = m.y * sigmoidf_(v1);
                }
                *(float2*)(crow + col) = make_float2(v0, v1);
                if (C2) *(uint32_t*)(c2row + col) = pack2h(v0, v1);
            }
        }
}

// ---------------------------------------------------------------------------
// Small kernels
// ---------------------------------------------------------------------------
__global__ void transpose_kernel(const float* __restrict__ src, float* __restrict__ dst,
                                 int R, int C)
{
    __shared__ float t[32][33];
    int bx = blockIdx.x * 32, by = blockIdx.y * 32;
#pragma unroll
    for (int j = 0; j < 32; j += 8)
        t[threadIdx.y + j][threadIdx.x] = src[(size_t)(by + threadIdx.y + j) * C + bx + threadIdx.x];
    __syncthreads();
#pragma unroll
    for (int j = 0; j < 32; j += 8)
        dst[(size_t)(bx + threadIdx.y + j) * R + by + threadIdx.x] = t[threadIdx.x][threadIdx.y + j];
}

// f32 -> f16 (rn), 8 elems/thread
__global__ void f2h_kernel(const float4* __restrict__ x, uint4* __restrict__ y, int n8)
{
    int i = blockIdx.x * 256 + threadIdx.x;
    if (i >= n8) return;
    float4 v0 = x[2 * i], v1 = x[2 * i + 1];
    uint4 o;
    o.x = pack2h(v0.x, v0.y);
    o.y = pack2h(v0.z, v0.w);
    o.z = pack2h(v1.x, v1.y);
    o.w = pack2h(v1.z, v1.w);
    y[i] = o;
}

// f32 -> hi/lo fp16 split
__global__ void split_h_kernel(const float* __restrict__ x,
                               __half* __restrict__ hi, __half* __restrict__ lo, int n)
{
    int i = blockIdx.x * 256 + threadIdx.x;
    if (i >= n) return;
    float v = x[i];
    __half h = __float2half_rn(v);
    hi[i] = h;
    lo[i] = __float2half_rn(v - __half2float(h));
}

// dst(f32) = sum_z part
__global__ void reduce_zf_kernel(const float4* __restrict__ part, float4* __restrict__ dst,
                                 int n4, int Z, int s4)
{
    int i = blockIdx.x * 256 + threadIdx.x;
    if (i >= n4) return;
    float4 a = part[i];
    for (int z = 1; z < Z; z++) {
        float4 v = part[i + z * s4];
        a.x += v.x; a.y += v.y; a.z += v.z; a.w += v.w;
    }
    dst[i] = a;
}

// dst(f16) = rn(sum_z part)
__global__ void reduce_zh_kernel(const float4* __restrict__ part, uint2* __restrict__ dst,
                                 int n4, int Z, int s4)
{
    int i = blockIdx.x * 256 + threadIdx.x;
    if (i >= n4) return;
    float4 a = part[i];
    for (int z = 1; z < Z; z++) {
        float4 v = part[i + z * s4];
        a.x += v.x; a.y += v.y; a.z += v.z; a.w += v.w;
    }
    uint2 o;
    o.x = pack2h(a.x, a.y);
    o.y = pack2h(a.z, a.w);
    dst[i] = o;
}

__global__ void gemv_kernel(const float* __restrict__ W, int ldw,
                            const float* __restrict__ x, const float* __restrict__ b,
                            float* __restrict__ y, int N, int K)
{
    int row = blockIdx.x * 8 + (threadIdx.x >> 5);
    int lane = threadIdx.x & 31;
    if (row >= N) return;
    float s = 0.0f;
    for (int k = lane; k < K; k += 32) s += W[(size_t)row * ldw + k] * x[k];
#pragma unroll
    for (int o = 16; o > 0; o >>= 1) s += __shfl_down_sync(0xFFFFFFFFu, s, o);
    if (lane == 0) y[row] = s + (b ? b[row] : 0.0f);
}

__global__ void ew_gru_kernel(const float4* __restrict__ gi,
                              const float4* __restrict__ gh,
                              const float4* __restrict__ gated,
                              float4* __restrict__ upd,
                              uint2* __restrict__ updh, int n4)
{
    int i = blockIdx.x * 256 + threadIdx.x;
    if (i >= n4) return;
    const int M4 = MEM_DIM / 4;
    int b = i / M4, j = i - b * M4;
    size_t base = (size_t)b * (NGATE / 4);
    float4 gir = gi[base + j],          ghr = gh[base + j];
    float4 giz = gi[base + M4 + j],     ghz = gh[base + M4 + j];
    float4 gin = gi[base + 2 * M4 + j], ghn = gh[base + 2 * M4 + j];
    float4 gd = gated[i];
    float4 u;
    {
        float r = sigmoidf_(gir.x + ghr.x), z = sigmoidf_(giz.x + ghz.x);
        u.x = (1.0f - z) * tanhf(gin.x + r * ghn.x) + z * gd.x;
    }
    {
        float r = sigmoidf_(gir.y + ghr.y), z = sigmoidf_(giz.y + ghz.y);
        u.y = (1.0f - z) * tanhf(gin.y + r * ghn.y) + z * gd.y;
    }
    {
        float r = sigmoidf_(gir.z + ghr.z), z = sigmoidf_(giz.z + ghz.z);
        u.z = (1.0f - z) * tanhf(gin.z + r * ghn.z) + z * gd.z;
    }
    {
        float r = sigmoidf_(gir.w + ghr.w), z = sigmoidf_(giz.w + ghz.w);
        u.w = (1.0f - z) * tanhf(gin.w + r * ghn.w) + z * gd.w;
    }
    upd[i] = u;
    uint2 o;
    o.x = pack2h(u.x, u.y);
    o.y = pack2h(u.z, u.w);
    updh[i] = o;
}

__global__ void fill_ones_kernel(float* __restrict__ out, int n)
{
    int idx = blockIdx.x * blockDim.x + threadIdx.x;
    if (idx < n) out[idx] = 1.0f;
}

// ---------------------------------------------------------------------------
// Launch
// ---------------------------------------------------------------------------
extern "C" void kernel_launch(void* const* d_in, const int* in_sizes, int n_in,
                              void* d_out, int out_size)
{
    const float* input      = (const float*)d_in[0];
    const float* prev       = (const float*)d_in[1];
    const float* in_proj_w  = (const float*)d_in[2];
    const float* in_proj_b  = (const float*)d_in[3];
    const float* out_proj_w = (const float*)d_in[4];
    const float* out_proj_b = (const float*)d_in[5];
    const float* ip_w       = (const float*)d_in[6];
    const float* ip_b       = (const float*)d_in[7];
    // d_in[8..9] mp_w/mp_b dead: softmax over a single key == 1
    const float* fg_w       = (const float*)d_in[10];
    const float* fg_b       = (const float*)d_in[11];
    const float* og_w       = (const float*)d_in[12];
    const float* og_b       = (const float*)d_in[13];
    const float* w_ih       = (const float*)d_in[14];
    const float* b_ih       = (const float*)d_in[15];
    const float* w_hh       = (const float*)d_in[16];
    const float* b_hh       = (const float*)d_in[17];
    float* out = (float*)d_out;

    const float* wv = in_proj_w + 2 * CTX_DIM * CTX_DIM;
    const float* bv = in_proj_b + 2 * CTX_DIM;

    float *ipT, *m1t, *m2t, *part, *b1, *b2, *bgi, *gi, *gh, *gated, *upd;
    __half *inh, *pvh, *fgwh, *whhh, *ogwh, *wgih, *gth, *udh, *sAh, *sAl, *sBh, *sBl;
    cudaGetSymbolAddress((void**)&ipT,  g_ipT);
    cudaGetSymbolAddress((void**)&m1t,  g_m1t);
    cudaGetSymbolAddress((void**)&m2t,  g_m2t);
    cudaGetSymbolAddress((void**)&part, g_part);
    cudaGetSymbolAddress((void**)&b1,   g_b1);
    cudaGetSymbolAddress((void**)&b2,   g_b2);
    cudaGetSymbolAddress((void**)&bgi,  g_bgi);
    cudaGetSymbolAddress((void**)&gi,   g_gi);
    cudaGetSymbolAddress((void**)&gh,   g_gh);
    cudaGetSymbolAddress((void**)&gated, g_gated);
    cudaGetSymbolAddress((void**)&upd,  g_upd);
    cudaGetSymbolAddress((void**)&inh,  g_inh);
    cudaGetSymbolAddress((void**)&pvh,  g_pvh);
    cudaGetSymbolAddress((void**)&fgwh, g_fgwh);
    cudaGetSymbolAddress((void**)&whhh, g_whhh);
    cudaGetSymbolAddress((void**)&ogwh, g_ogwh);
    cudaGetSymbolAddress((void**)&wgih, g_wgih);
    cudaGetSymbolAddress((void**)&gth,  g_gth);
    cudaGetSymbolAddress((void**)&udh,  g_udh);
    cudaGetSymbolAddress((void**)&sAh,  g_sAh);
    cudaGetSymbolAddress((void**)&sAl,  g_sAl);
    cudaGetSymbolAddress((void**)&sBh,  g_sBh);
    cudaGetSymbolAddress((void**)&sBl,  g_sBl);

    cudaFuncSetAttribute(h16_gemm, cudaFuncAttributeMaxDynamicSharedMemorySize, SMEM_DYN);

    const Seg Z = {nullptr, 0, nullptr, 0, 0};
    const int NSQ = CTX_DIM * CTX_DIM;

    // bias folds (fp32 GEMV)
    gemv_kernel<<<CTX_DIM / 8, 256>>>(wv,         CTX_DIM, ip_b, bv,         b1,  CTX_DIM, CTX_DIM);
    gemv_kernel<<<CTX_DIM / 8, 256>>>(out_proj_w, CTX_DIM, b1,   out_proj_b, b2,  CTX_DIM, CTX_DIM);
    gemv_kernel<<<NGATE   / 8, 256>>>(w_ih,       CTX_DIM, b2,   b_ih,       bgi, NGATE,   CTX_DIM);

    // fp16 operand staging
    f2h_kernel<<<(BB * IN_DIM / 8) / 256, 256>>>((const float4*)input, (uint4*)inh, BB * IN_DIM / 8);
    f2h_kernel<<<(BB * MEM_DIM / 8) / 256, 256>>>((const float4*)prev, (uint4*)pvh, BB * MEM_DIM / 8);
    f2h_kernel<<<(MEM_DIM * (MEM_DIM + IN_DIM) / 8) / 256, 256>>>(
        (const float4*)fg_w, (uint4*)fgwh, MEM_DIM * (MEM_DIM + IN_DIM) / 8);
    f2h_kernel<<<(NGATE * MEM_DIM / 8) / 256, 256>>>((const float4*)w_hh, (uint4*)whhh, NGATE * MEM_DIM / 8);
    f2h_kernel<<<(MEM_DIM * MEM_DIM / 8) / 256, 256>>>((const float4*)og_w, (uint4*)ogwh, MEM_DIM * MEM_DIM / 8);

    // FG: gated = prev * sigmoid(prev@fgA^T + input@fgB^T + fg_b); also gth (f16)
    {
        Seg a = {pvh, MEM_DIM, fgwh,           MEM_DIM + IN_DIM, MEM_DIM};
        Seg b = {inh, IN_DIM,  fgwh + MEM_DIM, MEM_DIM + IN_DIM, IN_DIM};
        h16_gemm<<<dim3(MEM_DIM / BN, BB / BM), 256, SMEM_DYN>>>(
            a, b, Z, fg_b, prev, gated, gth, MEM_DIM, 1, 0);
    }
    // GH = gated @ w_hh^T + b_hh
    {
        Seg a = {gth, MEM_DIM, whhh, MEM_DIM, MEM_DIM};
        h16_gemm<<<dim3(NGATE / BN, BB / BM), 256, SMEM_DYN>>>(
            a, Z, Z, b_hh, nullptr, gh, nullptr, NGATE, 0, 0);
    }

    // ---- weight folds: 3-pass fp16 hi/lo compensation, split-K Z=4 ----
    transpose_kernel<<<dim3(IN_DIM / 32, CTX_DIM / 32), dim3(32, 8)>>>(ip_w, ipT, CTX_DIM, IN_DIM);
    split_h_kernel<<<NSQ / 256, 256>>>(ipT, sAh, sAl, NSQ);
    split_h_kernel<<<NSQ / 256, 256>>>(wv,  sBh, sBl, NSQ);
    {   // M1T[IN,CTX] = ip_w^T @ wv^T
        Seg a = {sAh, CTX_DIM, sBh, CTX_DIM, CTX_DIM};
        Seg b = {sAh, CTX_DIM, sBl, CTX_DIM, CTX_DIM};
        Seg c = {sAl, CTX_DIM, sBh, CTX_DIM, CTX_DIM};
        h16_gemm<<<dim3(CTX_DIM / BN, IN_DIM / BM, ZSPLIT), 256, SMEM_DYN>>>(
            a, b, c, nullptr, nullptr, part, nullptr, CTX_DIM, 0, IN_DIM);
        reduce_zf_kernel<<<(NSQ / 4) / 256, 256>>>(
            (const float4*)part, (float4*)m1t, NSQ / 4, ZSPLIT, NSQ / 4);
    }
    split_h_kernel<<<NSQ / 256, 256>>>(m1t,        sAh, sAl, NSQ);
    split_h_kernel<<<NSQ / 256, 256>>>(out_proj_w, sBh, sBl, NSQ);
    {   // M2T[IN,CTX] = M1T @ out_proj_w^T
        Seg a = {sAh, CTX_DIM, sBh, CTX_DIM, CTX_DIM};
        Seg b = {sAh, CTX_DIM, sBl, CTX_DIM, CTX_DIM};
        Seg c = {sAl, CTX_DIM, sBh, CTX_DIM, CTX_DIM};
        h16_gemm<<<dim3(CTX_DIM / BN, IN_DIM / BM, ZSPLIT), 256, SMEM_DYN>>>(
            a, b, c, nullptr, nullptr, part, nullptr, CTX_DIM, 0, IN_DIM);
        reduce_zf_kernel<<<(NSQ / 4) / 256, 256>>>(
            (const float4*)part, (float4*)m2t, NSQ / 4, ZSPLIT, NSQ / 4);
    }
    split_h_kernel<<<(NGATE * CTX_DIM) / 256, 256>>>(w_ih, sAh, sAl, NGATE * CTX_DIM);
    split_h_kernel<<<NSQ / 256, 256>>>(m2t, sBh, sBl, NSQ);
    {   // WGIH[NGATE,IN] = rn16(w_ih @ M2T^T)
        Seg a = {sAh, CTX_DIM, sBh, CTX_DIM, CTX_DIM};
        Seg b = {sAh, CTX_DIM, sBl, CTX_DIM, CTX_DIM};
        Seg c = {sAl, CTX_DIM, sBh, CTX_DIM, CTX_DIM};
        h16_gemm<<<dim3(IN_DIM / BN, NGATE / BM, ZSPLIT), 256, SMEM_DYN>>>(
            a, b, c, nullptr, nullptr, part, nullptr, IN_DIM, 0, NGATE);
        reduce_zh_kernel<<<(NGATE * IN_DIM / 4) / 256, 256>>>(
            (const float4*)part, (uint2*)wgih, NGATE * IN_DIM / 4, ZSPLIT, NGATE * IN_DIM / 4);
    }

    // GI = input @ WGI^T + bgi
    {
        Seg a = {inh, IN_DIM, wgih, IN_DIM, IN_DIM};
        h16_gemm<<<dim3(NGATE / BN, BB / BM), 256, SMEM_DYN>>>(
            a, Z, Z, bgi, nullptr, gi, nullptr, NGATE, 0, 0);
    }
    // GRU elementwise -> upd (f32) + udh (f16)
    ew_gru_kernel<<<(BB * MEM_DIM / 4) / 256, 256>>>(
        (const float4*)gi, (const float4*)gh, (const float4*)gated,
        (float4*)upd, (uint2*)udh, BB * MEM_DIM / 4);
    // out = upd * sigmoid(upd @ og_w^T + og_b)
    {
        Seg a = {udh, MEM_DIM, ogwh, MEM_DIM, MEM_DIM};
        h16_gemm<<<dim3(MEM_DIM / BN, BB / BM), 256, SMEM_DYN>>>(
            a, Z, Z, og_b, upd, out, nullptr, MEM_DIM, 1, 0);
    }
    // attention weights: softmax over single key == 1.0
    int tail = out_size - BB * MEM_DIM;
    if (tail > 0)
        fill_ones_kernel<<<(tail + 255) / 256, 256>>>(out + BB * MEM_DIM, tail);
}

// round 7
// speedup vs baseline: 5.4410x; 1.1251x over previous
#include <cuda_runtime.h>
#include <cuda_fp16.h>
#include <math.h>
#include <stdint.h>

#define BB      8192
#define IN_DIM  1024
#define MEM_DIM 1024
#define CTX_DIM 1024
#define NGATE   3072

// ---- fp16 GEMM tiling ----
#define BM 128
#define BN 128
#define BK 64
#define LDH 72                     // halfs per smem row (144B; ldmatrix conflict-free)
#define STG 3
#define TILE_H (BM * LDH)          // 9216 halfs = 18432 B
#define STAGE_B (2 * TILE_H * 2)   // 36864 B
#define SMEM_DYN (STG * STAGE_B)   // 110592 B

#define ZSPLIT 4

// ---------------------------------------------------------------------------
// Device scratch
// ---------------------------------------------------------------------------
__device__ __align__(256) float  g_ipT [IN_DIM * CTX_DIM];
__device__ __align__(256) float  g_m1t [IN_DIM * CTX_DIM];
__device__ __align__(256) float  g_m2t [IN_DIM * CTX_DIM];
__device__ __align__(256) float  g_part[ZSPLIT * NGATE * IN_DIM];
__device__ __align__(256) float  g_b1  [CTX_DIM];
__device__ __align__(256) float  g_b2  [CTX_DIM];
__device__ __align__(256) float  g_bgi [NGATE];
__device__ __align__(256) float  g_gi  [(size_t)BB * NGATE];
__device__ __align__(256) float  g_gh  [(size_t)BB * NGATE];
__device__ __align__(256) float  g_gated[(size_t)BB * MEM_DIM];
__device__ __align__(256) float  g_upd [(size_t)BB * MEM_DIM];
// fp16 operands
__device__ __align__(256) __half g_inh [(size_t)BB * IN_DIM];
__device__ __align__(256) __half g_pvh [(size_t)BB * MEM_DIM];
__device__ __align__(256) __half g_fgwh[MEM_DIM * (MEM_DIM + IN_DIM)];
__device__ __align__(256) __half g_whhh[NGATE * MEM_DIM];
__device__ __align__(256) __half g_ogwh[MEM_DIM * MEM_DIM];
__device__ __align__(256) __half g_wgih[NGATE * IN_DIM];
__device__ __align__(256) __half g_gth [(size_t)BB * MEM_DIM];
__device__ __align__(256) __half g_udh [(size_t)BB * MEM_DIM];
__device__ __align__(256) __half g_sAh [NGATE * CTX_DIM];
__device__ __align__(256) __half g_sAl [NGATE * CTX_DIM];
__device__ __align__(256) __half g_sBh [CTX_DIM * CTX_DIM];
__device__ __align__(256) __half g_sBl [CTX_DIM * CTX_DIM];

// ---------------------------------------------------------------------------
// Helpers
// ---------------------------------------------------------------------------
__device__ __forceinline__ float sigmoidf_(float x) { return 1.0f / (1.0f + expf(-x)); }
__device__ __forceinline__ uint32_t pack2h(float a, float b) {
    __half2 h = __float22half2_rn(make_float2(a, b));
    return *(uint32_t*)&h;
}

// ---------------------------------------------------------------------------
// Segmented fp16 mma.sync GEMM (f32 accum), single-sync multistage pipeline,
// ldmatrix fragment loads, optional split-K via blockIdx.z.
//   pre[m,n] = sum_seg sum_k A_seg[m,k]*B_seg[n,k]  (+bias[n])
//   mode 0: C = pre      mode 1: C = mul * sigmoid(pre)
//   C2 (half, optional): half copy of C.
// A_seg [M,K] row-major halfs, B_seg [N,K] row-major halfs. K_seg mult of 64.
// ---------------------------------------------------------------------------
struct Seg { const __half* A; int lda; const __half* B; int ldb; int K; };

__global__ __launch_bounds__(256, 2)
void h16_gemm(Seg s0, Seg s1, Seg s2,
              const float* __restrict__ bias,
              const float* __restrict__ mul,
              float* __restrict__ C, __half* __restrict__ C2,
              int ldc, int mode, int partM)
{
    extern __shared__ __half smh[];
    uint32_t sbase;
    asm("{ .reg .u64 t; cvta.to.shared.u64 t, %1; cvt.u32.u64 %0, t; }"
        : "=r"(sbase) : "l"(smh));

    const int tid = threadIdx.x;
    const int wid = tid >> 5, lid = tid & 31;
    const int g = lid >> 2, tg = lid & 3;
    const int wm = wid & 3, wn = wid >> 2;          // warps: 4(M) x 2(N)
    const int row0 = blockIdx.y * BM, col0 = blockIdx.x * BN;

    const int e0 = s0.K / BK;
    const int e1 = e0 + s1.K / BK;
    const int niter_tot = e1 + s2.K / BK;
    const int cnt = niter_tot / gridDim.z;
    const int it0 = blockIdx.z * cnt;
    const int it1 = it0 + cnt;

    C += (size_t)blockIdx.z * partM * ldc;

    const __half* A0 = s0.A + (size_t)row0 * s0.lda;
    const __half* B0 = s0.B + (size_t)col0 * s0.ldb;
    const __half* A1 = s1.A ? s1.A + (size_t)row0 * s1.lda : A0;
    const __half* B1 = s1.B ? s1.B + (size_t)col0 * s1.ldb : B0;
    const __half* A2 = s2.A ? s2.A + (size_t)row0 * s2.lda : A0;
    const __half* B2 = s2.B ? s2.B + (size_t)col0 * s2.ldb : B0;

    // ldmatrix lane-derived byte offsets (stride 144B rows)
    const int lr   = lid & 7;
    const int s1b  = (lid >> 3) & 1;
    const int cby  = (lid >> 4) * 16;   // +8 halfs for mats 2,3
    uint32_t offA[2], offB[4];
#pragma unroll
    for (int mt = 0; mt < 2; mt++)
        offA[mt] = (uint32_t)((wm * 32 + mt * 16 + lr + s1b * 8) * 144 + cby);
#pragma unroll
    for (int p = 0; p < 4; p++)
        offB[p] = (uint32_t)((wn * 64 + p * 16 + lr + s1b * 8) * 144 + cby);

    auto load_stage = [&](int s, int kc) {
        const __half* Ag; const __half* Bg; int lda, ldb, k0;
        if (kc < e0)      { Ag = A0; Bg = B0; lda = s0.lda; ldb = s0.ldb; k0 = kc * BK; }
        else if (kc < e1) { Ag = A1; Bg = B1; lda = s1.lda; ldb = s1.ldb; k0 = (kc - e0) * BK; }
        else              { Ag = A2; Bg = B2; lda = s2.lda; ldb = s2.ldb; k0 = (kc - e1) * BK; }
        const uint32_t sa = sbase + (uint32_t)s * STAGE_B;
        const uint32_t sb = sa + TILE_H * 2;
#pragma unroll
        for (int i = 0; i < 4; i++) {           // A: 128 rows x 8 chunks
            int c = tid + i * 256, r = c >> 3, ch = c & 7;
            asm volatile("cp.async.cg.shared.global [%0], [%1], 16;"
                :: "r"(sa + (uint32_t)(r * 144 + ch * 16)),
                   "l"(Ag + (size_t)r * lda + k0 + ch * 8) : "memory");
        }
#pragma unroll
        for (int i = 0; i < 4; i++) {           // B
            int c = tid + i * 256, r = c >> 3, ch = c & 7;
            asm volatile("cp.async.cg.shared.global [%0], [%1], 16;"
                :: "r"(sb + (uint32_t)(r * 144 + ch * 16)),
                   "l"(Bg + (size_t)r * ldb + k0 + ch * 8) : "memory");
        }
    };

    float acc[2][8][4];
#pragma unroll
    for (int mt = 0; mt < 2; mt++)
#pragma unroll
        for (int nt = 0; nt < 8; nt++)
#pragma unroll
            for (int e = 0; e < 4; e++) acc[mt][nt][e] = 0.0f;

    // prologue: STG-1 stages
    for (int p = 0; p < STG - 1; p++) {
        load_stage(p, it0 + p);
        asm volatile("cp.async.commit_group;" ::: "memory");
    }

    for (int it = it0; it < it1; it++) {
        asm volatile("cp.async.wait_group %0;" :: "n"(STG - 2) : "memory");
        __syncthreads();                         // single barrier per iter

        const uint32_t Au = sbase + (uint32_t)((it - it0) % STG) * STAGE_B;
        const uint32_t Bu = Au + TILE_H * 2;
#pragma unroll
        for (int ks = 0; ks < 4; ks++) {         // 4 x k16 per BK=64
            const uint32_t kbb = ks * 32;        // 16 halfs = 32 bytes
            uint32_t af[2][4], bf[8][2];
#pragma unroll
            for (int mt = 0; mt < 2; mt++)
                asm volatile("ldmatrix.sync.aligned.m8n8.x4.shared.b16 {%0,%1,%2,%3}, [%4];"
                    : "=r"(af[mt][0]), "=r"(af[mt][1]), "=r"(af[mt][2]), "=r"(af[mt][3])
                    : "r"(Au + offA[mt] + kbb));
#pragma unroll
            for (int p = 0; p < 4; p++) {
                uint32_t q0, q1, q2, q3;
                asm volatile("ldmatrix.sync.aligned.m8n8.x4.shared.b16 {%0,%1,%2,%3}, [%4];"
                    : "=r"(q0), "=r"(q1), "=r"(q2), "=r"(q3)
                    : "r"(Bu + offB[p] + kbb));
                bf[2 * p][0] = q0; bf[2 * p + 1][0] = q1;
                bf[2 * p][1] = q2; bf[2 * p + 1][1] = q3;
            }
#pragma unroll
            for (int mt = 0; mt < 2; mt++)
#pragma unroll
                for (int nt = 0; nt < 8; nt++)
                    asm volatile(
                        "mma.sync.aligned.m16n8k16.row.col.f32.f16.f16.f32 "
                        "{%0,%1,%2,%3}, {%4,%5,%6,%7}, {%8,%9}, {%0,%1,%2,%3};"
                        : "+f"(acc[mt][nt][0]), "+f"(acc[mt][nt][1]),
                          "+f"(acc[mt][nt][2]), "+f"(acc[mt][nt][3])
                        : "r"(af[mt][0]), "r"(af[mt][1]), "r"(af[mt][2]), "r"(af[mt][3]),
                          "r"(bf[nt][0]), "r"(bf[nt][1]));
        }

        const int pre = it + STG - 1;
        if (pre < it1) load_stage((pre - it0) % STG, pre);
        asm volatile("cp.async.commit_group;" ::: "memory");
    }

    // ---- epilogue ----
#pragma unroll
    for (int mt = 0; mt < 2; mt++)
#pragma unroll
        for (int h = 0; h < 2; h++) {
            const int row = row0 + wm * 32 + mt * 16 + g + h * 8;
            float* crow        = C + (size_t)row * ldc + col0 + wn * 64;
            const float* mrow  = mul ? mul + (size_t)row * ldc + col0 + wn * 64 : nullptr;
            __half* c2row      = C2 ? C2 + (size_t)row * ldc + col0 + wn * 64 : nullptr;
#pragma unroll
            for (int nt = 0; nt < 8; nt++) {
                const int col = nt * 8 + 2 * tg;
                float v0 = acc[mt][nt][h * 2 + 0];
                float v1 = acc[mt][nt][h * 2 + 1];
                if (bias) {
                    v0 += bias[col0 + wn * 64 + col];
                    v1 += bias[col0 + wn * 64 + col + 1];
                }
                if (mode == 1) {
                    float2 m = *(const float2*)(mrow + col);
                    v0 = m.x * sigmoidf_(v0);
                    v1 = m.y * sigmoidf_(v1);
                }
                *(float2*)(crow + col) = make_float2(v0, v1);
                if (C2) *(uint32_t*)(c2row + col) = pack2h(v0, v1);
            }
        }
}

// ---------------------------------------------------------------------------
// Small kernels
// ---------------------------------------------------------------------------
__global__ void transpose_kernel(const float* __restrict__ src, float* __restrict__ dst,
                                 int R, int C)
{
    __shared__ float t[32][33];
    int bx = blockIdx.x * 32, by = blockIdx.y * 32;
#pragma unroll
    for (int j = 0; j < 32; j += 8)
        t[threadIdx.y + j][threadIdx.x] = src[(size_t)(by + threadIdx.y + j) * C + bx + threadIdx.x];
    __syncthreads();
#pragma unroll
    for (int j = 0; j < 32; j += 8)
        dst[(size_t)(bx + threadIdx.y + j) * R + by + threadIdx.x] = t[threadIdx.x][threadIdx.y + j];
}

__global__ void f2h_kernel(const float4* __restrict__ x, uint4* __restrict__ y, int n8)
{
    int i = blockIdx.x * 256 + threadIdx.x;
    if (i >= n8) return;
    float4 v0 = x[2 * i], v1 = x[2 * i + 1];
    uint4 o;
    o.x = pack2h(v0.x, v0.y);
    o.y = pack2h(v0.z, v0.w);
    o.z = pack2h(v1.x, v1.y);
    o.w = pack2h(v1.z, v1.w);
    y[i] = o;
}

__global__ void split_h_kernel(const float* __restrict__ x,
                               __half* __restrict__ hi, __half* __restrict__ lo, int n)
{
    int i = blockIdx.x * 256 + threadIdx.x;
    if (i >= n) return;
    float v = x[i];
    __half h = __float2half_rn(v);
    hi[i] = h;
    lo[i] = __float2half_rn(v - __half2float(h));
}

__global__ void reduce_zf_kernel(const float4* __restrict__ part, float4* __restrict__ dst,
                                 int n4, int Z, int s4)
{
    int i = blockIdx.x * 256 + threadIdx.x;
    if (i >= n4) return;
    float4 a = part[i];
    for (int z = 1; z < Z; z++) {
        float4 v = part[i + z * s4];
        a.x += v.x; a.y += v.y; a.z += v.z; a.w += v.w;
    }
    dst[i] = a;
}

__global__ void reduce_zh_kernel(const float4* __restrict__ part, uint2* __restrict__ dst,
                                 int n4, int Z, int s4)
{
    int i = blockIdx.x * 256 + threadIdx.x;
    if (i >= n4) return;
    float4 a = part[i];
    for (int z = 1; z < Z; z++) {
        float4 v = part[i + z * s4];
        a.x += v.x; a.y += v.y; a.z += v.z; a.w += v.w;
    }
    uint2 o;
    o.x = pack2h(a.x, a.y);
    o.y = pack2h(a.z, a.w);
    dst[i] = o;
}

__global__ void gemv_kernel(const float* __restrict__ W, int ldw,
                            const float* __restrict__ x, const float* __restrict__ b,
                            float* __restrict__ y, int N, int K)
{
    int row = blockIdx.x * 8 + (threadIdx.x >> 5);
    int lane = threadIdx.x & 31;
    if (row >= N) return;
    float s = 0.0f;
    for (int k = lane; k < K; k += 32) s += W[(size_t)row * ldw + k] * x[k];
#pragma unroll
    for (int o = 16; o > 0; o >>= 1) s += __shfl_down_sync(0xFFFFFFFFu, s, o);
    if (lane == 0) y[row] = s + (b ? b[row] : 0.0f);
}

__global__ void ew_gru_kernel(const float4* __restrict__ gi,
                              const float4* __restrict__ gh,
                              const float4* __restrict__ gated,
                              float4* __restrict__ upd,
                              uint2* __restrict__ updh, int n4)
{
    int i = blockIdx.x * 256 + threadIdx.x;
    if (i >= n4) return;
    const int M4 = MEM_DIM / 4;
    int b = i / M4, j = i - b * M4;
    size_t base = (size_t)b * (NGATE / 4);
    float4 gir = gi[base + j],          ghr = gh[base + j];
    float4 giz = gi[base + M4 + j],     ghz = gh[base + M4 + j];
    float4 gin = gi[base + 2 * M4 + j], ghn = gh[base + 2 * M4 + j];
    float4 gd = gated[i];
    float4 u;
    {
        float r = sigmoidf_(gir.x + ghr.x), z = sigmoidf_(giz.x + ghz.x);
        u.x = (1.0f - z) * tanhf(gin.x + r * ghn.x) + z * gd.x;
    }
    {
        float r = sigmoidf_(gir.y + ghr.y), z = sigmoidf_(giz.y + ghz.y);
        u.y = (1.0f - z) * tanhf(gin.y + r * ghn.y) + z * gd.y;
    }
    {
        float r = sigmoidf_(gir.z + ghr.z), z = sigmoidf_(giz.z + ghz.z);
        u.z = (1.0f - z) * tanhf(gin.z + r * ghn.z) + z * gd.z;
    }
    {
        float r = sigmoidf_(gir.w + ghr.w), z = sigmoidf_(giz.w + ghz.w);
        u.w = (1.0f - z) * tanhf(gin.w + r * ghn.w) + z * gd.w;
    }
    upd[i] = u;
    uint2 o;
    o.x = pack2h(u.x, u.y);
    o.y = pack2h(u.z, u.w);
    updh[i] = o;
}

__global__ void fill_ones_kernel(float* __restrict__ out, int n)
{
    int idx = blockIdx.x * blockDim.x + threadIdx.x;
    if (idx < n) out[idx] = 1.0f;
}

// ---------------------------------------------------------------------------
// Launch
// ---------------------------------------------------------------------------
extern "C" void kernel_launch(void* const* d_in, const int* in_sizes, int n_in,
                              void* d_out, int out_size)
{
    const float* input      = (const float*)d_in[0];
    const float* prev       = (const float*)d_in[1];
    const float* in_proj_w  = (const float*)d_in[2];
    const float* in_proj_b  = (const float*)d_in[3];
    const float* out_proj_w = (const float*)d_in[4];
    const float* out_proj_b = (const float*)d_in[5];
    const float* ip_w       = (const float*)d_in[6];
    const float* ip_b       = (const float*)d_in[7];
    // d_in[8..9] mp_w/mp_b dead: softmax over a single key == 1
    const float* fg_w       = (const float*)d_in[10];
    const float* fg_b       = (const float*)d_in[11];
    const float* og_w       = (const float*)d_in[12];
    const float* og_b       = (const float*)d_in[13];
    const float* w_ih       = (const float*)d_in[14];
    const float* b_ih       = (const float*)d_in[15];
    const float* w_hh       = (const float*)d_in[16];
    const float* b_hh       = (const float*)d_in[17];
    float* out = (float*)d_out;

    const float* wv = in_proj_w + 2 * CTX_DIM * CTX_DIM;
    const float* bv = in_proj_b + 2 * CTX_DIM;

    float *ipT, *m1t, *m2t, *part, *b1, *b2, *bgi, *gi, *gh, *gated, *upd;
    __half *inh, *pvh, *fgwh, *whhh, *ogwh, *wgih, *gth, *udh, *sAh, *sAl, *sBh, *sBl;
    cudaGetSymbolAddress((void**)&ipT,  g_ipT);
    cudaGetSymbolAddress((void**)&m1t,  g_m1t);
    cudaGetSymbolAddress((void**)&m2t,  g_m2t);
    cudaGetSymbolAddress((void**)&part, g_part);
    cudaGetSymbolAddress((void**)&b1,   g_b1);
    cudaGetSymbolAddress((void**)&b2,   g_b2);
    cudaGetSymbolAddress((void**)&bgi,  g_bgi);
    cudaGetSymbolAddress((void**)&gi,   g_gi);
    cudaGetSymbolAddress((void**)&gh,   g_gh);
    cudaGetSymbolAddress((void**)&gated, g_gated);
    cudaGetSymbolAddress((void**)&upd,  g_upd);
    cudaGetSymbolAddress((void**)&inh,  g_inh);
    cudaGetSymbolAddress((void**)&pvh,  g_pvh);
    cudaGetSymbolAddress((void**)&fgwh, g_fgwh);
    cudaGetSymbolAddress((void**)&whhh, g_whhh);
    cudaGetSymbolAddress((void**)&ogwh, g_ogwh);
    cudaGetSymbolAddress((void**)&wgih, g_wgih);
    cudaGetSymbolAddress((void**)&gth,  g_gth);
    cudaGetSymbolAddress((void**)&udh,  g_udh);
    cudaGetSymbolAddress((void**)&sAh,  g_sAh);
    cudaGetSymbolAddress((void**)&sAl,  g_sAl);
    cudaGetSymbolAddress((void**)&sBh,  g_sBh);
    cudaGetSymbolAddress((void**)&sBl,  g_sBl);

    cudaFuncSetAttribute(h16_gemm, cudaFuncAttributeMaxDynamicSharedMemorySize, SMEM_DYN);

    const Seg Z = {nullptr, 0, nullptr, 0, 0};
    const int NSQ = CTX_DIM * CTX_DIM;

    // #0-2: fp16 staging needed by FG
    f2h_kernel<<<(BB * IN_DIM / 8) / 256, 256>>>((const float4*)input, (uint4*)inh, BB * IN_DIM / 8);
    f2h_kernel<<<(BB * MEM_DIM / 8) / 256, 256>>>((const float4*)prev, (uint4*)pvh, BB * MEM_DIM / 8);
    f2h_kernel<<<(MEM_DIM * (MEM_DIM + IN_DIM) / 8) / 256, 256>>>(
        (const float4*)fg_w, (uint4*)fgwh, MEM_DIM * (MEM_DIM + IN_DIM) / 8);
    // #3-4: first two bias-fold GEMVs
    gemv_kernel<<<CTX_DIM / 8, 256>>>(wv,         CTX_DIM, ip_b, bv,         b1, CTX_DIM, CTX_DIM);
    gemv_kernel<<<CTX_DIM / 8, 256>>>(out_proj_w, CTX_DIM, b1,   out_proj_b, b2, CTX_DIM, CTX_DIM);

    // #5: FG GEMM (ncu profiles launch index 5)
    {
        Seg a = {pvh, MEM_DIM, fgwh,           MEM_DIM + IN_DIM, MEM_DIM};
        Seg b = {inh, IN_DIM,  fgwh + MEM_DIM, MEM_DIM + IN_DIM, IN_DIM};
        h16_gemm<<<dim3(MEM_DIM / BN, BB / BM), 256, SMEM_DYN>>>(
            a, b, Z, fg_b, prev, gated, gth, MEM_DIM, 1, 0);
    }

    // remaining staging + third GEMV
    f2h_kernel<<<(NGATE * MEM_DIM / 8) / 256, 256>>>((const float4*)w_hh, (uint4*)whhh, NGATE * MEM_DIM / 8);
    f2h_kernel<<<(MEM_DIM * MEM_DIM / 8) / 256, 256>>>((const float4*)og_w, (uint4*)ogwh, MEM_DIM * MEM_DIM / 8);
    gemv_kernel<<<NGATE / 8, 256>>>(w_ih, CTX_DIM, b2, b_ih, bgi, NGATE, CTX_DIM);

    // GH = gated @ w_hh^T + b_hh
    {
        Seg a = {gth, MEM_DIM, whhh, MEM_DIM, MEM_DIM};
        h16_gemm<<<dim3(NGATE / BN, BB / BM), 256, SMEM_DYN>>>(
            a, Z, Z, b_hh, nullptr, gh, nullptr, NGATE, 0, 0);
    }

    // ---- weight folds: 3-pass fp16 hi/lo compensation, split-K Z=4 ----
    transpose_kernel<<<dim3(IN_DIM / 32, CTX_DIM / 32), dim3(32, 8)>>>(ip_w, ipT, CTX_DIM, IN_DIM);
    split_h_kernel<<<NSQ / 256, 256>>>(ipT, sAh, sAl, NSQ);
    split_h_kernel<<<NSQ / 256, 256>>>(wv,  sBh, sBl, NSQ);
    {   // M1T[IN,CTX] = ip_w^T @ wv^T
        Seg a = {sAh, CTX_DIM, sBh, CTX_DIM, CTX_DIM};
        Seg b = {sAh, CTX_DIM, sBl, CTX_DIM, CTX_DIM};
        Seg c = {sAl, CTX_DIM, sBh, CTX_DIM, CTX_DIM};
        h16_gemm<<<dim3(CTX_DIM / BN, IN_DIM / BM, ZSPLIT), 256, SMEM_DYN>>>(
            a, b, c, nullptr, nullptr, part, nullptr, CTX_DIM, 0, IN_DIM);
        reduce_zf_kernel<<<(NSQ / 4) / 256, 256>>>(
            (const float4*)part, (float4*)m1t, NSQ / 4, ZSPLIT, NSQ / 4);
    }
    split_h_kernel<<<NSQ / 256, 256>>>(m1t,        sAh, sAl, NSQ);
    split_h_kernel<<<NSQ / 256, 256>>>(out_proj_w, sBh, sBl, NSQ);
    {   // M2T[IN,CTX] = M1T @ out_proj_w^T
        Seg a = {sAh, CTX_DIM, sBh, CTX_DIM, CTX_DIM};
        Seg b = {sAh, CTX_DIM, sBl, CTX_DIM, CTX_DIM};
        Seg c = {sAl, CTX_DIM, sBh, CTX_DIM, CTX_DIM};
        h16_gemm<<<dim3(CTX_DIM / BN, IN_DIM / BM, ZSPLIT), 256, SMEM_DYN>>>(
            a, b, c, nullptr, nullptr, part, nullptr, CTX_DIM, 0, IN_DIM);
        reduce_zf_kernel<<<(NSQ / 4) / 256, 256>>>(
            (const float4*)part, (float4*)m2t, NSQ / 4, ZSPLIT, NSQ / 4);
    }
    split_h_kernel<<<(NGATE * CTX_DIM) / 256, 256>>>(w_ih, sAh, sAl, NGATE * CTX_DIM);
    split_h_kernel<<<NSQ / 256, 256>>>(m2t, sBh, sBl, NSQ);
    {   // WGIH[NGATE,IN] = rn16(w_ih @ M2T^T)
        Seg a = {sAh, CTX_DIM, sBh, CTX_DIM, CTX_DIM};
        Seg b = {sAh, CTX_DIM, sBl, CTX_DIM, CTX_DIM};
        Seg c = {sAl, CTX_DIM, sBh, CTX_DIM, CTX_DIM};
        h16_gemm<<<dim3(IN_DIM / BN, NGATE / BM, ZSPLIT), 256, SMEM_DYN>>>(
            a, b, c, nullptr, nullptr, part, nullptr, IN_DIM, 0, NGATE);
        reduce_zh_kernel<<<(NGATE * IN_DIM / 4) / 256, 256>>>(
            (const float4*)part, (uint2*)wgih, NGATE * IN_DIM / 4, ZSPLIT, NGATE * IN_DIM / 4);
    }

    // GI = input @ WGI^T + bgi
    {
        Seg a = {inh, IN_DIM, wgih, IN_DIM, IN_DIM};
        h16_gemm<<<dim3(NGATE / BN, BB / BM), 256, SMEM_DYN>>>(
            a, Z, Z, bgi, nullptr, gi, nullptr, NGATE, 0, 0);
    }
    // GRU elementwise -> upd (f32) + udh (f16)
    ew_gru_kernel<<<(BB * MEM_DIM / 4) / 256, 256>>>(
        (const float4*)gi, (const float4*)gh, (const float4*)gated,
        (float4*)upd, (uint2*)udh, BB * MEM_DIM / 4);
    // out = upd * sigmoid(upd @ og_w^T + og_b)
    {
        Seg a = {udh, MEM_DIM, ogwh, MEM_DIM, MEM_DIM};
        h16_gemm<<<dim3(MEM_DIM / BN, BB / BM), 256, SMEM_DYN>>>(
            a, Z, Z, og_b, upd, out, nullptr, MEM_DIM, 1, 0);
    }
    // attention weights: softmax over single key == 1.0
    int tail = out_size - BB * MEM_DIM;
    if (tail > 0)
        fill_ones_kernel<<<(tail + 255) / 256, 256>>>(out + BB * MEM_DIM, tail);
}

// round 8
// speedup vs baseline: 5.5636x; 1.0225x over previous
#include <cuda_runtime.h>
#include <cuda_fp16.h>
#include <math.h>
#include <stdint.h>

#define BB      8192
#define IN_DIM  1024
#define MEM_DIM 1024
#define CTX_DIM 1024
#define NGATE   3072

// ---- fp16 GEMM tiling ----
#define BM 128
#define BN 128
#define BK 64
#define LDH 72                     // halfs per smem row (144B; ldmatrix conflict-free)
#define STG 3
#define TILE_H (BM * LDH)          // 9216 halfs = 18432 B
#define STAGE_B (2 * TILE_H * 2)   // 36864 B
#define SMEM_DYN (STG * STAGE_B)   // 110592 B

#define ZSPLIT 4

// ---------------------------------------------------------------------------
// Device scratch
// ---------------------------------------------------------------------------
__device__ __align__(256) float  g_ipT [IN_DIM * CTX_DIM];
__device__ __align__(256) float  g_m1t [IN_DIM * CTX_DIM];
__device__ __align__(256) float  g_m2t [IN_DIM * CTX_DIM];
__device__ __align__(256) float  g_part[ZSPLIT * NGATE * IN_DIM];
__device__ __align__(256) float  g_b1  [CTX_DIM];
__device__ __align__(256) float  g_b2  [CTX_DIM];
__device__ __align__(256) float  g_bgi [NGATE];
__device__ __align__(256) float  g_upd [(size_t)BB * MEM_DIM];
// fp16 operands / intermediates
__device__ __align__(256) __half g_inh [(size_t)BB * IN_DIM];
__device__ __align__(256) __half g_pvh [(size_t)BB * MEM_DIM];
__device__ __align__(256) __half g_fgwh[MEM_DIM * (MEM_DIM + IN_DIM)];
__device__ __align__(256) __half g_whhh[NGATE * MEM_DIM];
__device__ __align__(256) __half g_ogwh[MEM_DIM * MEM_DIM];
__device__ __align__(256) __half g_wgih[NGATE * IN_DIM];
__device__ __align__(256) __half g_gth [(size_t)BB * MEM_DIM];
__device__ __align__(256) __half g_udh [(size_t)BB * MEM_DIM];
__device__ __align__(256) __half g_gih [(size_t)BB * NGATE];
__device__ __align__(256) __half g_ghh [(size_t)BB * NGATE];
__device__ __align__(256) __half g_sAh [NGATE * CTX_DIM];
__device__ __align__(256) __half g_sAl [NGATE * CTX_DIM];
__device__ __align__(256) __half g_sBh [CTX_DIM * CTX_DIM];
__device__ __align__(256) __half g_sBl [CTX_DIM * CTX_DIM];

// ---------------------------------------------------------------------------
// Helpers
// ---------------------------------------------------------------------------
__device__ __forceinline__ float sigmoidf_(float x) { return 1.0f / (1.0f + expf(-x)); }
__device__ __forceinline__ uint32_t pack2h(float a, float b) {
    __half2 h = __float22half2_rn(make_float2(a, b));
    return *(uint32_t*)&h;
}
__device__ __forceinline__ float4 up4(uint2 u) {
    float2 a = __half22float2(*(__half2*)&u.x);
    float2 b = __half22float2(*(__half2*)&u.y);
    return make_float4(a.x, a.y, b.x, b.y);
}

// ---------------------------------------------------------------------------
// Segmented fp16 mma.sync GEMM (f32 accum), single-sync multistage pipeline,
// ldmatrix fragment loads, optional split-K via blockIdx.z.
//   pre[m,n] = sum_seg sum_k A_seg[m,k]*B_seg[n,k]  (+bias[n])
//   mode 0: v = pre      mode 1: v = mul * sigmoid(pre)
//   C (f32, optional) and/or C2 (f16, optional) receive v.
// A_seg [M,K] row-major halfs, B_seg [N,K] row-major halfs. K_seg mult of 64.
// ---------------------------------------------------------------------------
struct Seg { const __half* A; int lda; const __half* B; int ldb; int K; };

__global__ __launch_bounds__(256, 2)
void h16_gemm(Seg s0, Seg s1, Seg s2,
              const float* __restrict__ bias,
              const float* __restrict__ mul,
              float* __restrict__ C, __half* __restrict__ C2,
              int ldc, int mode, int partM)
{
    extern __shared__ __half smh[];
    uint32_t sbase;
    asm("{ .reg .u64 t; cvta.to.shared.u64 t, %1; cvt.u32.u64 %0, t; }"
        : "=r"(sbase) : "l"(smh));

    const int tid = threadIdx.x;
    const int wid = tid >> 5, lid = tid & 31;
    const int g = lid >> 2, tg = lid & 3;
    const int wm = wid & 3, wn = wid >> 2;          // warps: 4(M) x 2(N)
    const int row0 = blockIdx.y * BM, col0 = blockIdx.x * BN;

    const int e0 = s0.K / BK;
    const int e1 = e0 + s1.K / BK;
    const int niter_tot = e1 + s2.K / BK;
    const int cnt = niter_tot / gridDim.z;
    const int it0 = blockIdx.z * cnt;
    const int it1 = it0 + cnt;

    if (C)  C  += (size_t)blockIdx.z * partM * ldc;
    if (C2) C2 += (size_t)blockIdx.z * partM * ldc;

    const __half* A0 = s0.A + (size_t)row0 * s0.lda;
    const __half* B0 = s0.B + (size_t)col0 * s0.ldb;
    const __half* A1 = s1.A ? s1.A + (size_t)row0 * s1.lda : A0;
    const __half* B1 = s1.B ? s1.B + (size_t)col0 * s1.ldb : B0;
    const __half* A2 = s2.A ? s2.A + (size_t)row0 * s2.lda : A0;
    const __half* B2 = s2.B ? s2.B + (size_t)col0 * s2.ldb : B0;

    // ldmatrix lane-derived byte offsets (stride 144B rows)
    const int lr   = lid & 7;
    const int s1b  = (lid >> 3) & 1;
    const int cby  = (lid >> 4) * 16;
    uint32_t offA[2], offB[4];
#pragma unroll
    for (int mt = 0; mt < 2; mt++)
        offA[mt] = (uint32_t)((wm * 32 + mt * 16 + lr + s1b * 8) * 144 + cby);
#pragma unroll
    for (int p = 0; p < 4; p++)
        offB[p] = (uint32_t)((wn * 64 + p * 16 + lr + s1b * 8) * 144 + cby);

    auto load_stage = [&](int s, int kc) {
        const __half* Ag; const __half* Bg; int lda, ldb, k0;
        if (kc < e0)      { Ag = A0; Bg = B0; lda = s0.lda; ldb = s0.ldb; k0 = kc * BK; }
        else if (kc < e1) { Ag = A1; Bg = B1; lda = s1.lda; ldb = s1.ldb; k0 = (kc - e0) * BK; }
        else              { Ag = A2; Bg = B2; lda = s2.lda; ldb = s2.ldb; k0 = (kc - e1) * BK; }
        const uint32_t sa = sbase + (uint32_t)s * STAGE_B;
        const uint32_t sb = sa + TILE_H * 2;
#pragma unroll
        for (int i = 0; i < 4; i++) {
            int c = tid + i * 256, r = c >> 3, ch = c & 7;
            asm volatile("cp.async.cg.shared.global [%0], [%1], 16;"
                :: "r"(sa + (uint32_t)(r * 144 + ch * 16)),
                   "l"(Ag + (size_t)r * lda + k0 + ch * 8) : "memory");
        }
#pragma unroll
        for (int i = 0; i < 4; i++) {
            int c = tid + i * 256, r = c >> 3, ch = c & 7;
            asm volatile("cp.async.cg.shared.global [%0], [%1], 16;"
                :: "r"(sb + (uint32_t)(r * 144 + ch * 16)),
                   "l"(Bg + (size_t)r * ldb + k0 + ch * 8) : "memory");
        }
    };

    float acc[2][8][4];
#pragma unroll
    for (int mt = 0; mt < 2; mt++)
#pragma unroll
        for (int nt = 0; nt < 8; nt++)
#pragma unroll
            for (int e = 0; e < 4; e++) acc[mt][nt][e] = 0.0f;

    for (int p = 0; p < STG - 1; p++) {
        load_stage(p, it0 + p);
        asm volatile("cp.async.commit_group;" ::: "memory");
    }

    for (int it = it0; it < it1; it++) {
        asm volatile("cp.async.wait_group %0;" :: "n"(STG - 2) : "memory");
        __syncthreads();

        const uint32_t Au = sbase + (uint32_t)((it - it0) % STG) * STAGE_B;
        const uint32_t Bu = Au + TILE_H * 2;
#pragma unroll
        for (int ks = 0; ks < 4; ks++) {
            const uint32_t kbb = ks * 32;
            uint32_t af[2][4], bf[8][2];
#pragma unroll
            for (int mt = 0; mt < 2; mt++)
                asm volatile("ldmatrix.sync.aligned.m8n8.x4.shared.b16 {%0,%1,%2,%3}, [%4];"
                    : "=r"(af[mt][0]), "=r"(af[mt][1]), "=r"(af[mt][2]), "=r"(af[mt][3])
                    : "r"(Au + offA[mt] + kbb));
#pragma unroll
            for (int p = 0; p < 4; p++) {
                uint32_t q0, q1, q2, q3;
                asm volatile("ldmatrix.sync.aligned.m8n8.x4.shared.b16 {%0,%1,%2,%3}, [%4];"
                    : "=r"(q0), "=r"(q1), "=r"(q2), "=r"(q3)
                    : "r"(Bu + offB[p] + kbb));
                bf[2 * p][0] = q0; bf[2 * p + 1][0] = q1;
                bf[2 * p][1] = q2; bf[2 * p + 1][1] = q3;
            }
#pragma unroll
            for (int mt = 0; mt < 2; mt++)
#pragma unroll
                for (int nt = 0; nt < 8; nt++)
                    asm volatile(
                        "mma.sync.aligned.m16n8k16.row.col.f32.f16.f16.f32 "
                        "{%0,%1,%2,%3}, {%4,%5,%6,%7}, {%8,%9}, {%0,%1,%2,%3};"
                        : "+f"(acc[mt][nt][0]), "+f"(acc[mt][nt][1]),
                          "+f"(acc[mt][nt][2]), "+f"(acc[mt][nt][3])
                        : "r"(af[mt][0]), "r"(af[mt][1]), "r"(af[mt][2]), "r"(af[mt][3]),
                          "r"(bf[nt][0]), "r"(bf[nt][1]));
        }

        const int pre = it + STG - 1;
        if (pre < it1) load_stage((pre - it0) % STG, pre);
        asm volatile("cp.async.commit_group;" ::: "memory");
    }

    // ---- epilogue ----
#pragma unroll
    for (int mt = 0; mt < 2; mt++)
#pragma unroll
        for (int h = 0; h < 2; h++) {
            const int row = row0 + wm * 32 + mt * 16 + g + h * 8;
            float* crow        = C  ? C  + (size_t)row * ldc + col0 + wn * 64 : nullptr;
            const float* mrow  = mul ? mul + (size_t)row * ldc + col0 + wn * 64 : nullptr;
            __half* c2row      = C2 ? C2 + (size_t)row * ldc + col0 + wn * 64 : nullptr;
#pragma unroll
            for (int nt = 0; nt < 8; nt++) {
                const int col = nt * 8 + 2 * tg;
                float v0 = acc[mt][nt][h * 2 + 0];
                float v1 = acc[mt][nt][h * 2 + 1];
                if (bias) {
                    v0 += bias[col0 + wn * 64 + col];
                    v1 += bias[col0 + wn * 64 + col + 1];
                }
                if (mode == 1) {
                    float2 m = *(const float2*)(mrow + col);
                    v0 = m.x * sigmoidf_(v0);
                    v1 = m.y * sigmoidf_(v1);
                }
                if (crow)  *(float2*)(crow + col) = make_float2(v0, v1);
                if (c2row) *(uint32_t*)(c2row + col) = pack2h(v0, v1);
            }
        }
}

// ---------------------------------------------------------------------------
// Small kernels
// ---------------------------------------------------------------------------
__global__ void transpose_kernel(const float* __restrict__ src, float* __restrict__ dst,
                                 int R, int C)
{
    __shared__ float t[32][33];
    int bx = blockIdx.x * 32, by = blockIdx.y * 32;
#pragma unroll
    for (int j = 0; j < 32; j += 8)
        t[threadIdx.y + j][threadIdx.x] = src[(size_t)(by + threadIdx.y + j) * C + bx + threadIdx.x];
    __syncthreads();
#pragma unroll
    for (int j = 0; j < 32; j += 8)
        dst[(size_t)(bx + threadIdx.y + j) * R + by + threadIdx.x] = t[threadIdx.x][threadIdx.y + j];
}

__global__ void f2h_kernel(const float4* __restrict__ x, uint4* __restrict__ y, int n8)
{
    int i = blockIdx.x * 256 + threadIdx.x;
    if (i >= n8) return;
    float4 v0 = x[2 * i], v1 = x[2 * i + 1];
    uint4 o;
    o.x = pack2h(v0.x, v0.y);
    o.y = pack2h(v0.z, v0.w);
    o.z = pack2h(v1.x, v1.y);
    o.w = pack2h(v1.z, v1.w);
    y[i] = o;
}

__global__ void split_h_kernel(const float* __restrict__ x,
                               __half* __restrict__ hi, __half* __restrict__ lo, int n)
{
    int i = blockIdx.x * 256 + threadIdx.x;
    if (i >= n) return;
    float v = x[i];
    __half h = __float2half_rn(v);
    hi[i] = h;
    lo[i] = __float2half_rn(v - __half2float(h));
}

__global__ void reduce_zf_kernel(const float4* __restrict__ part, float4* __restrict__ dst,
                                 int n4, int Z, int s4)
{
    int i = blockIdx.x * 256 + threadIdx.x;
    if (i >= n4) return;
    float4 a = part[i];
    for (int z = 1; z < Z; z++) {
        float4 v = part[i + z * s4];
        a.x += v.x; a.y += v.y; a.z += v.z; a.w += v.w;
    }
    dst[i] = a;
}

__global__ void reduce_zh_kernel(const float4* __restrict__ part, uint2* __restrict__ dst,
                                 int n4, int Z, int s4)
{
    int i = blockIdx.x * 256 + threadIdx.x;
    if (i >= n4) return;
    float4 a = part[i];
    for (int z = 1; z < Z; z++) {
        float4 v = part[i + z * s4];
        a.x += v.x; a.y += v.y; a.z += v.z; a.w += v.w;
    }
    uint2 o;
    o.x = pack2h(a.x, a.y);
    o.y = pack2h(a.z, a.w);
    dst[i] = o;
}

__global__ void gemv_kernel(const float* __restrict__ W, int ldw,
                            const float* __restrict__ x, const float* __restrict__ b,
                            float* __restrict__ y, int N, int K)
{
    int row = blockIdx.x * 8 + (threadIdx.x >> 5);
    int lane = threadIdx.x & 31;
    if (row >= N) return;
    float s = 0.0f;
    for (int k = lane; k < K; k += 32) s += W[(size_t)row * ldw + k] * x[k];
#pragma unroll
    for (int o = 16; o > 0; o >>= 1) s += __shfl_down_sync(0xFFFFFFFFu, s, o);
    if (lane == 0) y[row] = s + (b ? b[row] : 0.0f);
}

// GRU elementwise: gi/gh/gated in fp16, upd out f32 + f16
__global__ void ew_gru_kernel(const uint2* __restrict__ gih,
                              const uint2* __restrict__ ghh,
                              const uint2* __restrict__ gth,
                              float4* __restrict__ upd,
                              uint2* __restrict__ updh, int n4)
{
    int i = blockIdx.x * 256 + threadIdx.x;
    if (i >= n4) return;
    const int M4 = MEM_DIM / 4;
    int b = i / M4, j = i - b * M4;
    size_t base = (size_t)b * (NGATE / 4);
    float4 gir = up4(gih[base + j]),          ghr = up4(ghh[base + j]);
    float4 giz = up4(gih[base + M4 + j]),     ghz = up4(ghh[base + M4 + j]);
    float4 gin = up4(gih[base + 2 * M4 + j]), ghn = up4(ghh[base + 2 * M4 + j]);
    float4 gd = up4(gth[i]);
    float4 u;
    {
        float r = sigmoidf_(gir.x + ghr.x), z = sigmoidf_(giz.x + ghz.x);
        u.x = (1.0f - z) * tanhf(gin.x + r * ghn.x) + z * gd.x;
    }
    {
        float r = sigmoidf_(gir.y + ghr.y), z = sigmoidf_(giz.y + ghz.y);
        u.y = (1.0f - z) * tanhf(gin.y + r * ghn.y) + z * gd.y;
    }
    {
        float r = sigmoidf_(gir.z + ghr.z), z = sigmoidf_(giz.z + ghz.z);
        u.z = (1.0f - z) * tanhf(gin.z + r * ghn.z) + z * gd.z;
    }
    {
        float r = sigmoidf_(gir.w + ghr.w), z = sigmoidf_(giz.w + ghz.w);
        u.w = (1.0f - z) * tanhf(gin.w + r * ghn.w) + z * gd.w;
    }
    upd[i] = u;
    uint2 o;
    o.x = pack2h(u.x, u.y);
    o.y = pack2h(u.z, u.w);
    updh[i] = o;
}

__global__ void fill_ones_kernel(float* __restrict__ out, int n)
{
    int idx = blockIdx.x * blockDim.x + threadIdx.x;
    if (idx < n) out[idx] = 1.0f;
}

// ---------------------------------------------------------------------------
// Launch
// ---------------------------------------------------------------------------
extern "C" void kernel_launch(void* const* d_in, const int* in_sizes, int n_in,
                              void* d_out, int out_size)
{
    const float* input      = (const float*)d_in[0];
    const float* prev       = (const float*)d_in[1];
    const float* in_proj_w  = (const float*)d_in[2];
    const float* in_proj_b  = (const float*)d_in[3];
    const float* out_proj_w = (const float*)d_in[4];
    const float* out_proj_b = (const float*)d_in[5];
    const float* ip_w       = (const float*)d_in[6];
    const float* ip_b       = (const float*)d_in[7];
    // d_in[8..9] mp_w/mp_b dead: softmax over a single key == 1
    const float* fg_w       = (const float*)d_in[10];
    const float* fg_b       = (const float*)d_in[11];
    const float* og_w       = (const float*)d_in[12];
    const float* og_b       = (const float*)d_in[13];
    const float* w_ih       = (const float*)d_in[14];
    const float* b_ih       = (const float*)d_in[15];
    const float* w_hh       = (const float*)d_in[16];
    const float* b_hh       = (const float*)d_in[17];
    float* out = (float*)d_out;

    const float* wv = in_proj_w + 2 * CTX_DIM * CTX_DIM;
    const float* bv = in_proj_b + 2 * CTX_DIM;

    float *ipT, *m1t, *m2t, *part, *b1, *b2, *bgi, *upd;
    __half *inh, *pvh, *fgwh, *whhh, *ogwh, *wgih, *gth, *udh, *gih, *ghh;
    __half *sAh, *sAl, *sBh, *sBl;
    cudaGetSymbolAddress((void**)&ipT,  g_ipT);
    cudaGetSymbolAddress((void**)&m1t,  g_m1t);
    cudaGetSymbolAddress((void**)&m2t,  g_m2t);
    cudaGetSymbolAddress((void**)&part, g_part);
    cudaGetSymbolAddress((void**)&b1,   g_b1);
    cudaGetSymbolAddress((void**)&b2,   g_b2);
    cudaGetSymbolAddress((void**)&bgi,  g_bgi);
    cudaGetSymbolAddress((void**)&upd,  g_upd);
    cudaGetSymbolAddress((void**)&inh,  g_inh);
    cudaGetSymbolAddress((void**)&pvh,  g_pvh);
    cudaGetSymbolAddress((void**)&fgwh, g_fgwh);
    cudaGetSymbolAddress((void**)&whhh, g_whhh);
    cudaGetSymbolAddress((void**)&ogwh, g_ogwh);
    cudaGetSymbolAddress((void**)&wgih, g_wgih);
    cudaGetSymbolAddress((void**)&gth,  g_gth);
    cudaGetSymbolAddress((void**)&udh,  g_udh);
    cudaGetSymbolAddress((void**)&gih,  g_gih);
    cudaGetSymbolAddress((void**)&ghh,  g_ghh);
    cudaGetSymbolAddress((void**)&sAh,  g_sAh);
    cudaGetSymbolAddress((void**)&sAl,  g_sAl);
    cudaGetSymbolAddress((void**)&sBh,  g_sBh);
    cudaGetSymbolAddress((void**)&sBl,  g_sBl);

    cudaFuncSetAttribute(h16_gemm, cudaFuncAttributeMaxDynamicSharedMemorySize, SMEM_DYN);

    const Seg Z = {nullptr, 0, nullptr, 0, 0};
    const int NSQ = CTX_DIM * CTX_DIM;

    // launches 0-3: staging needed by FG
    f2h_kernel<<<(BB * IN_DIM / 8) / 256, 256>>>((const float4*)input, (uint4*)inh, BB * IN_DIM / 8);
    f2h_kernel<<<(BB * MEM_DIM / 8) / 256, 256>>>((const float4*)prev, (uint4*)pvh, BB * MEM_DIM / 8);
    f2h_kernel<<<(MEM_DIM * (MEM_DIM + IN_DIM) / 8) / 256, 256>>>(
        (const float4*)fg_w, (uint4*)fgwh, MEM_DIM * (MEM_DIM + IN_DIM) / 8);
    gemv_kernel<<<CTX_DIM / 8, 256>>>(wv, CTX_DIM, ip_b, bv, b1, CTX_DIM, CTX_DIM);

    // launch index 4 (ncu capture target): FG GEMM
    // gth = rn16(prev * sigmoid(prev@fgA^T + input@fgB^T + fg_b))
    {
        Seg a = {pvh, MEM_DIM, fgwh,           MEM_DIM + IN_DIM, MEM_DIM};
        Seg b = {inh, IN_DIM,  fgwh + MEM_DIM, MEM_DIM + IN_DIM, IN_DIM};
        h16_gemm<<<dim3(MEM_DIM / BN, BB / BM), 256, SMEM_DYN>>>(
            a, b, Z, fg_b, prev, nullptr, gth, MEM_DIM, 1, 0);
    }

    // remaining staging + bias folds
    f2h_kernel<<<(NGATE * MEM_DIM / 8) / 256, 256>>>((const float4*)w_hh, (uint4*)whhh, NGATE * MEM_DIM / 8);
    f2h_kernel<<<(MEM_DIM * MEM_DIM / 8) / 256, 256>>>((const float4*)og_w, (uint4*)ogwh, MEM_DIM * MEM_DIM / 8);
    gemv_kernel<<<CTX_DIM / 8, 256>>>(out_proj_w, CTX_DIM, b1, out_proj_b, b2, CTX_DIM, CTX_DIM);
    gemv_kernel<<<NGATE / 8, 256>>>(w_ih, CTX_DIM, b2, b_ih, bgi, NGATE, CTX_DIM);

    // GH (f16 out): ghh = rn16(gated @ w_hh^T + b_hh)
    {
        Seg a = {gth, MEM_DIM, whhh, MEM_DIM, MEM_DIM};
        h16_gemm<<<dim3(NGATE / BN, BB / BM), 256, SMEM_DYN>>>(
            a, Z, Z, b_hh, nullptr, nullptr, ghh, NGATE, 0, 0);
    }

    // ---- weight folds: 3-pass fp16 hi/lo compensation, split-K Z=4 ----
    transpose_kernel<<<dim3(IN_DIM / 32, CTX_DIM / 32), dim3(32, 8)>>>(ip_w, ipT, CTX_DIM, IN_DIM);
    split_h_kernel<<<NSQ / 256, 256>>>(ipT, sAh, sAl, NSQ);
    split_h_kernel<<<NSQ / 256, 256>>>(wv,  sBh, sBl, NSQ);
    {   // M1T[IN,CTX] = ip_w^T @ wv^T
        Seg a = {sAh, CTX_DIM, sBh, CTX_DIM, CTX_DIM};
        Seg b = {sAh, CTX_DIM, sBl, CTX_DIM, CTX_DIM};
        Seg c = {sAl, CTX_DIM, sBh, CTX_DIM, CTX_DIM};
        h16_gemm<<<dim3(CTX_DIM / BN, IN_DIM / BM, ZSPLIT), 256, SMEM_DYN>>>(
            a, b, c, nullptr, nullptr, part, nullptr, CTX_DIM, 0, IN_DIM);
        reduce_zf_kernel<<<(NSQ / 4) / 256, 256>>>(
            (const float4*)part, (float4*)m1t, NSQ / 4, ZSPLIT, NSQ / 4);
    }
    split_h_kernel<<<NSQ / 256, 256>>>(m1t,        sAh, sAl, NSQ);
    split_h_kernel<<<NSQ / 256, 256>>>(out_proj_w, sBh, sBl, NSQ);
    {   // M2T[IN,CTX] = M1T @ out_proj_w^T
        Seg a = {sAh, CTX_DIM, sBh, CTX_DIM, CTX_DIM};
        Seg b = {sAh, CTX_DIM, sBl, CTX_DIM, CTX_DIM};
        Seg c = {sAl, CTX_DIM, sBh, CTX_DIM, CTX_DIM};
        h16_gemm<<<dim3(CTX_DIM / BN, IN_DIM / BM, ZSPLIT), 256, SMEM_DYN>>>(
            a, b, c, nullptr, nullptr, part, nullptr, CTX_DIM, 0, IN_DIM);
        reduce_zf_kernel<<<(NSQ / 4) / 256, 256>>>(
            (const float4*)part, (float4*)m2t, NSQ / 4, ZSPLIT, NSQ / 4);
    }
    split_h_kernel<<<(NGATE * CTX_DIM) / 256, 256>>>(w_ih, sAh, sAl, NGATE * CTX_DIM);
    split_h_kernel<<<NSQ / 256, 256>>>(m2t, sBh, sBl, NSQ);
    {   // WGIH[NGATE,IN] = rn16(w_ih @ M2T^T)
        Seg a = {sAh, CTX_DIM, sBh, CTX_DIM, CTX_DIM};
        Seg b = {sAh, CTX_DIM, sBl, CTX_DIM, CTX_DIM};
        Seg c = {sAl, CTX_DIM, sBh, CTX_DIM, CTX_DIM};
        h16_gemm<<<dim3(IN_DIM / BN, NGATE / BM, ZSPLIT), 256, SMEM_DYN>>>(
            a, b, c, nullptr, nullptr, part, nullptr, IN_DIM, 0, NGATE);
        reduce_zh_kernel<<<(NGATE * IN_DIM / 4) / 256, 256>>>(
            (const float4*)part, (uint2*)wgih, NGATE * IN_DIM / 4, ZSPLIT, NGATE * IN_DIM / 4);
    }

    // GI (f16 out): gih = rn16(input @ WGI^T + bgi)
    {
        Seg a = {inh, IN_DIM, wgih, IN_DIM, IN_DIM};
        h16_gemm<<<dim3(NGATE / BN, BB / BM), 256, SMEM_DYN>>>(
            a, Z, Z, bgi, nullptr, nullptr, gih, NGATE, 0, 0);
    }
    // GRU elementwise -> upd (f32) + udh (f16)
    ew_gru_kernel<<<(BB * MEM_DIM / 4) / 256, 256>>>(
        (const uint2*)gih, (const uint2*)ghh, (const uint2*)gth,
        (float4*)upd, (uint2*)udh, BB * MEM_DIM / 4);
    // out = upd * sigmoid(upd @ og_w^T + og_b)
    {
        Seg a = {udh, MEM_DIM, ogwh, MEM_DIM, MEM_DIM};
        h16_gemm<<<dim3(MEM_DIM / BN, BB / BM), 256, SMEM_DYN>>>(
            a, Z, Z, og_b, upd, out, nullptr, MEM_DIM, 1, 0);
    }
    // attention weights: softmax over single key == 1.0
    int tail = out_size - BB * MEM_DIM;
    if (tail > 0)
        fill_ones_kernel<<<(tail + 255) / 256, 256>>>(out + BB * MEM_DIM, tail);
}

// round 9
// speedup vs baseline: 6.2671x; 1.1265x over previous
#include <cuda_runtime.h>
#include <cuda_fp16.h>
#include <math.h>
#include <stdint.h>

#define BB      8192
#define IN_DIM  1024
#define MEM_DIM 1024
#define CTX_DIM 1024
#define NGATE   3072

// ---- fp16 GEMM tiling ----
#define BM 128
#define BN 128
#define BK 64
#define LDH 72                     // halfs per smem row (144B; ldmatrix conflict-free)
#define STG 3
#define TILE_H (BM * LDH)          // 9216 halfs = 18432 B
#define STAGE_B (2 * TILE_H * 2)   // 36864 B
#define SMEM_DYN (STG * STAGE_B)   // 110592 B

#define ZSPLIT 4

// ---------------------------------------------------------------------------
// Device scratch
// ---------------------------------------------------------------------------
__device__ __align__(256) float  g_part[ZSPLIT * NGATE * IN_DIM];
__device__ __align__(256) float  g_b1  [CTX_DIM];
__device__ __align__(256) float  g_b2  [CTX_DIM];
__device__ __align__(256) float  g_bgi [NGATE];
__device__ __align__(256) float  g_upd [(size_t)BB * MEM_DIM];
// fp16 operands / intermediates
__device__ __align__(256) __half g_inh [(size_t)BB * IN_DIM];
__device__ __align__(256) __half g_pvh [(size_t)BB * MEM_DIM];
__device__ __align__(256) __half g_fgwh[MEM_DIM * (MEM_DIM + IN_DIM)];
__device__ __align__(256) __half g_whhh[NGATE * MEM_DIM];
__device__ __align__(256) __half g_ogwh[MEM_DIM * MEM_DIM];
__device__ __align__(256) __half g_wgih[NGATE * IN_DIM];
__device__ __align__(256) __half g_gth [(size_t)BB * MEM_DIM];
__device__ __align__(256) __half g_udh [(size_t)BB * MEM_DIM];
__device__ __align__(256) __half g_gih [(size_t)BB * NGATE];
__device__ __align__(256) __half g_ghh [(size_t)BB * NGATE];
// fold-chain fp16 operands
__device__ __align__(256) __half g_iph [IN_DIM * CTX_DIM];   // ip_w^T, f16
__device__ __align__(256) __half g_wvh [CTX_DIM * CTX_DIM];
__device__ __align__(256) __half g_oph [CTX_DIM * CTX_DIM];
__device__ __align__(256) __half g_wihh[NGATE * CTX_DIM];
__device__ __align__(256) __half g_m1h [IN_DIM * CTX_DIM];
__device__ __align__(256) __half g_m2h [IN_DIM * CTX_DIM];

// ---------------------------------------------------------------------------
// Helpers
// ---------------------------------------------------------------------------
__device__ __forceinline__ float sigmoidf_(float x) { return 1.0f / (1.0f + expf(-x)); }
__device__ __forceinline__ uint32_t pack2h(float a, float b) {
    __half2 h = __float22half2_rn(make_float2(a, b));
    return *(uint32_t*)&h;
}
__device__ __forceinline__ float4 up4(uint2 u) {
    float2 a = __half22float2(*(__half2*)&u.x);
    float2 b = __half22float2(*(__half2*)&u.y);
    return make_float4(a.x, a.y, b.x, b.y);
}

// ---------------------------------------------------------------------------
// Segmented fp16 mma.sync GEMM (f32 accum), single-sync multistage pipeline,
// ldmatrix fragment loads, optional split-K via blockIdx.z.
//   pre[m,n] = sum_seg sum_k A_seg[m,k]*B_seg[n,k]  (+bias[n])
//   mode 0: v = pre      mode 1: v = mul * sigmoid(pre)
//   C (f32, optional) and/or C2 (f16, optional) receive v.
// ---------------------------------------------------------------------------
struct Seg { const __half* A; int lda; const __half* B; int ldb; int K; };

__global__ __launch_bounds__(256, 2)
void h16_gemm(Seg s0, Seg s1, Seg s2,
              const float* __restrict__ bias,
              const float* __restrict__ mul,
              float* __restrict__ C, __half* __restrict__ C2,
              int ldc, int mode, int partM)
{
    extern __shared__ __half smh[];
    uint32_t sbase;
    asm("{ .reg .u64 t; cvta.to.shared.u64 t, %1; cvt.u32.u64 %0, t; }"
        : "=r"(sbase) : "l"(smh));

    const int tid = threadIdx.x;
    const int wid = tid >> 5, lid = tid & 31;
    const int g = lid >> 2, tg = lid & 3;
    const int wm = wid & 3, wn = wid >> 2;          // warps: 4(M) x 2(N)
    const int row0 = blockIdx.y * BM, col0 = blockIdx.x * BN;

    const int e0 = s0.K / BK;
    const int e1 = e0 + s1.K / BK;
    const int niter_tot = e1 + s2.K / BK;
    const int cnt = niter_tot / gridDim.z;
    const int it0 = blockIdx.z * cnt;
    const int it1 = it0 + cnt;

    if (C)  C  += (size_t)blockIdx.z * partM * ldc;
    if (C2) C2 += (size_t)blockIdx.z * partM * ldc;

    const __half* A0 = s0.A + (size_t)row0 * s0.lda;
    const __half* B0 = s0.B + (size_t)col0 * s0.ldb;
    const __half* A1 = s1.A ? s1.A + (size_t)row0 * s1.lda : A0;
    const __half* B1 = s1.B ? s1.B + (size_t)col0 * s1.ldb : B0;
    const __half* A2 = s2.A ? s2.A + (size_t)row0 * s2.lda : A0;
    const __half* B2 = s2.B ? s2.B + (size_t)col0 * s2.ldb : B0;

    // ldmatrix lane-derived byte offsets (stride 144B rows)
    const int lr   = lid & 7;
    const int s1b  = (lid >> 3) & 1;
    const int cby  = (lid >> 4) * 16;
    uint32_t offA[2], offB[4];
#pragma unroll
    for (int mt = 0; mt < 2; mt++)
        offA[mt] = (uint32_t)((wm * 32 + mt * 16 + lr + s1b * 8) * 144 + cby);
#pragma unroll
    for (int p = 0; p < 4; p++)
        offB[p] = (uint32_t)((wn * 64 + p * 16 + lr + s1b * 8) * 144 + cby);

    auto load_stage = [&](int s, int kc) {
        const __half* Ag; const __half* Bg; int lda, ldb, k0;
        if (kc < e0)      { Ag = A0; Bg = B0; lda = s0.lda; ldb = s0.ldb; k0 = kc * BK; }
        else if (kc < e1) { Ag = A1; Bg = B1; lda = s1.lda; ldb = s1.ldb; k0 = (kc - e0) * BK; }
        else              { Ag = A2; Bg = B2; lda = s2.lda; ldb = s2.ldb; k0 = (kc - e1) * BK; }
        const uint32_t sa = sbase + (uint32_t)s * STAGE_B;
        const uint32_t sb = sa + TILE_H * 2;
#pragma unroll
        for (int i = 0; i < 4; i++) {
            int c = tid + i * 256, r = c >> 3, ch = c & 7;
            asm volatile("cp.async.cg.shared.global [%0], [%1], 16;"
                :: "r"(sa + (uint32_t)(r * 144 + ch * 16)),
                   "l"(Ag + (size_t)r * lda + k0 + ch * 8) : "memory");
        }
#pragma unroll
        for (int i = 0; i < 4; i++) {
            int c = tid + i * 256, r = c >> 3, ch = c & 7;
            asm volatile("cp.async.cg.shared.global [%0], [%1], 16;"
                :: "r"(sb + (uint32_t)(r * 144 + ch * 16)),
                   "l"(Bg + (size_t)r * ldb + k0 + ch * 8) : "memory");
        }
    };

    float acc[2][8][4];
#pragma unroll
    for (int mt = 0; mt < 2; mt++)
#pragma unroll
        for (int nt = 0; nt < 8; nt++)
#pragma unroll
            for (int e = 0; e < 4; e++) acc[mt][nt][e] = 0.0f;

    for (int p = 0; p < STG - 1; p++) {
        load_stage(p, it0 + p);
        asm volatile("cp.async.commit_group;" ::: "memory");
    }

    for (int it = it0; it < it1; it++) {
        asm volatile("cp.async.wait_group %0;" :: "n"(STG - 2) : "memory");
        __syncthreads();

        const uint32_t Au = sbase + (uint32_t)((it - it0) % STG) * STAGE_B;
        const uint32_t Bu = Au + TILE_H * 2;
#pragma unroll
        for (int ks = 0; ks < 4; ks++) {
            const uint32_t kbb = ks * 32;
            uint32_t af[2][4], bf[8][2];
#pragma unroll
            for (int mt = 0; mt < 2; mt++)
                asm volatile("ldmatrix.sync.aligned.m8n8.x4.shared.b16 {%0,%1,%2,%3}, [%4];"
                    : "=r"(af[mt][0]), "=r"(af[mt][1]), "=r"(af[mt][2]), "=r"(af[mt][3])
                    : "r"(Au + offA[mt] + kbb));
#pragma unroll
            for (int p = 0; p < 4; p++) {
                uint32_t q0, q1, q2, q3;
                asm volatile("ldmatrix.sync.aligned.m8n8.x4.shared.b16 {%0,%1,%2,%3}, [%4];"
                    : "=r"(q0), "=r"(q1), "=r"(q2), "=r"(q3)
                    : "r"(Bu + offB[p] + kbb));
                bf[2 * p][0] = q0; bf[2 * p + 1][0] = q1;
                bf[2 * p][1] = q2; bf[2 * p + 1][1] = q3;
            }
#pragma unroll
            for (int mt = 0; mt < 2; mt++)
#pragma unroll
                for (int nt = 0; nt < 8; nt++)
                    asm volatile(
                        "mma.sync.aligned.m16n8k16.row.col.f32.f16.f16.f32 "
                        "{%0,%1,%2,%3}, {%4,%5,%6,%7}, {%8,%9}, {%0,%1,%2,%3};"
                        : "+f"(acc[mt][nt][0]), "+f"(acc[mt][nt][1]),
                          "+f"(acc[mt][nt][2]), "+f"(acc[mt][nt][3])
                        : "r"(af[mt][0]), "r"(af[mt][1]), "r"(af[mt][2]), "r"(af[mt][3]),
                          "r"(bf[nt][0]), "r"(bf[nt][1]));
        }

        const int pre = it + STG - 1;
        if (pre < it1) load_stage((pre - it0) % STG, pre);
        asm volatile("cp.async.commit_group;" ::: "memory");
    }

    // ---- epilogue ----
#pragma unroll
    for (int mt = 0; mt < 2; mt++)
#pragma unroll
        for (int h = 0; h < 2; h++) {
            const int row = row0 + wm * 32 + mt * 16 + g + h * 8;
            float* crow        = C  ? C  + (size_t)row * ldc + col0 + wn * 64 : nullptr;
            const float* mrow  = mul ? mul + (size_t)row * ldc + col0 + wn * 64 : nullptr;
            __half* c2row      = C2 ? C2 + (size_t)row * ldc + col0 + wn * 64 : nullptr;
#pragma unroll
            for (int nt = 0; nt < 8; nt++) {
                const int col = nt * 8 + 2 * tg;
                float v0 = acc[mt][nt][h * 2 + 0];
                float v1 = acc[mt][nt][h * 2 + 1];
                if (bias) {
                    v0 += bias[col0 + wn * 64 + col];
                    v1 += bias[col0 + wn * 64 + col + 1];
                }
                if (mode == 1) {
                    float2 m = *(const float2*)(mrow + col);
                    v0 = m.x * sigmoidf_(v0);
                    v1 = m.y * sigmoidf_(v1);
                }
                if (crow)  *(float2*)(crow + col) = make_float2(v0, v1);
                if (c2row) *(uint32_t*)(c2row + col) = pack2h(v0, v1);
            }
        }
}

// ---------------------------------------------------------------------------
// Small kernels
// ---------------------------------------------------------------------------
// src[R,C] f32 -> dst[C,R] f16 (transpose + round)
__global__ void transpose_h_kernel(const float* __restrict__ src, __half* __restrict__ dst,
                                   int R, int C)
{
    __shared__ float t[32][33];
    int bx = blockIdx.x * 32, by = blockIdx.y * 32;
#pragma unroll
    for (int j = 0; j < 32; j += 8)
        t[threadIdx.y + j][threadIdx.x] = src[(size_t)(by + threadIdx.y + j) * C + bx + threadIdx.x];
    __syncthreads();
#pragma unroll
    for (int j = 0; j < 32; j += 8)
        dst[(size_t)(bx + threadIdx.y + j) * R + by + threadIdx.x] =
            __float2half_rn(t[threadIdx.x][threadIdx.y + j]);
}

__global__ void f2h_kernel(const float4* __restrict__ x, uint4* __restrict__ y, int n8)
{
    int i = blockIdx.x * 256 + threadIdx.x;
    if (i >= n8) return;
    float4 v0 = x[2 * i], v1 = x[2 * i + 1];
    uint4 o;
    o.x = pack2h(v0.x, v0.y);
    o.y = pack2h(v0.z, v0.w);
    o.z = pack2h(v1.x, v1.y);
    o.w = pack2h(v1.z, v1.w);
    y[i] = o;
}

// dst(f16) = rn(sum_z part)
__global__ void reduce_zh_kernel(const float4* __restrict__ part, uint2* __restrict__ dst,
                                 int n4, int Z, int s4)
{
    int i = blockIdx.x * 256 + threadIdx.x;
    if (i >= n4) return;
    float4 a = part[i];
    for (int z = 1; z < Z; z++) {
        float4 v = part[i + z * s4];
        a.x += v.x; a.y += v.y; a.z += v.z; a.w += v.w;
    }
    uint2 o;
    o.x = pack2h(a.x, a.y);
    o.y = pack2h(a.z, a.w);
    dst[i] = o;
}

__global__ void gemv_kernel(const float* __restrict__ W, int ldw,
                            const float* __restrict__ x, const float* __restrict__ b,
                            float* __restrict__ y, int N, int K)
{
    int row = blockIdx.x * 8 + (threadIdx.x >> 5);
    int lane = threadIdx.x & 31;
    if (row >= N) return;
    float s = 0.0f;
    for (int k = lane; k < K; k += 32) s += W[(size_t)row * ldw + k] * x[k];
#pragma unroll
    for (int o = 16; o > 0; o >>= 1) s += __shfl_down_sync(0xFFFFFFFFu, s, o);
    if (lane == 0) y[row] = s + (b ? b[row] : 0.0f);
}

// GRU elementwise: gi/gh/gated in fp16, upd out f32 + f16
__global__ void ew_gru_kernel(const uint2* __restrict__ gih,
                              const uint2* __restrict__ ghh,
                              const uint2* __restrict__ gth,
                              float4* __restrict__ upd,
                              uint2* __restrict__ updh, int n4)
{
    int i = blockIdx.x * 256 + threadIdx.x;
    if (i >= n4) return;
    const int M4 = MEM_DIM / 4;
    int b = i / M4, j = i - b * M4;
    size_t base = (size_t)b * (NGATE / 4);
    float4 gir = up4(gih[base + j]),          ghr = up4(ghh[base + j]);
    float4 giz = up4(gih[base + M4 + j]),     ghz = up4(ghh[base + M4 + j]);
    float4 gin = up4(gih[base + 2 * M4 + j]), ghn = up4(ghh[base + 2 * M4 + j]);
    float4 gd = up4(gth[i]);
    float4 u;
    {
        float r = sigmoidf_(gir.x + ghr.x), z = sigmoidf_(giz.x + ghz.x);
        u.x = (1.0f - z) * tanhf(gin.x + r * ghn.x) + z * gd.x;
    }
    {
        float r = sigmoidf_(gir.y + ghr.y), z = sigmoidf_(giz.y + ghz.y);
        u.y = (1.0f - z) * tanhf(gin.y + r * ghn.y) + z * gd.y;
    }
    {
        float r = sigmoidf_(gir.z + ghr.z), z = sigmoidf_(giz.z + ghz.z);
        u.z = (1.0f - z) * tanhf(gin.z + r * ghn.z) + z * gd.z;
    }
    {
        float r = sigmoidf_(gir.w + ghr.w), z = sigmoidf_(giz.w + ghz.w);
        u.w = (1.0f - z) * tanhf(gin.w + r * ghn.w) + z * gd.w;
    }
    upd[i] = u;
    uint2 o;
    o.x = pack2h(u.x, u.y);
    o.y = pack2h(u.z, u.w);
    updh[i] = o;
}

__global__ void fill_ones_kernel(float* __restrict__ out, int n)
{
    int idx = blockIdx.x * blockDim.x + threadIdx.x;
    if (idx < n) out[idx] = 1.0f;
}

// ---------------------------------------------------------------------------
// Launch
// ---------------------------------------------------------------------------
extern "C" void kernel_launch(void* const* d_in, const int* in_sizes, int n_in,
                              void* d_out, int out_size)
{
    const float* input      = (const float*)d_in[0];
    const float* prev       = (const float*)d_in[1];
    const float* in_proj_w  = (const float*)d_in[2];
    const float* in_proj_b  = (const float*)d_in[3];
    const float* out_proj_w = (const float*)d_in[4];
    const float* out_proj_b = (const float*)d_in[5];
    const float* ip_w       = (const float*)d_in[6];
    const float* ip_b       = (const float*)d_in[7];
    // d_in[8..9] mp_w/mp_b dead: softmax over a single key == 1
    const float* fg_w       = (const float*)d_in[10];
    const float* fg_b       = (const float*)d_in[11];
    const float* og_w       = (const float*)d_in[12];
    const float* og_b       = (const float*)d_in[13];
    const float* w_ih       = (const float*)d_in[14];
    const float* b_ih       = (const float*)d_in[15];
    const float* w_hh       = (const float*)d_in[16];
    const float* b_hh       = (const float*)d_in[17];
    float* out = (float*)d_out;

    const float* wv = in_proj_w + 2 * CTX_DIM * CTX_DIM;
    const float* bv = in_proj_b + 2 * CTX_DIM;

    float *part, *b1, *b2, *bgi, *upd;
    __half *inh, *pvh, *fgwh, *whhh, *ogwh, *wgih, *gth, *udh, *gih, *ghh;
    __half *iph, *wvh, *oph, *wihh, *m1h, *m2h;
    cudaGetSymbolAddress((void**)&part, g_part);
    cudaGetSymbolAddress((void**)&b1,   g_b1);
    cudaGetSymbolAddress((void**)&b2,   g_b2);
    cudaGetSymbolAddress((void**)&bgi,  g_bgi);
    cudaGetSymbolAddress((void**)&upd,  g_upd);
    cudaGetSymbolAddress((void**)&inh,  g_inh);
    cudaGetSymbolAddress((void**)&pvh,  g_pvh);
    cudaGetSymbolAddress((void**)&fgwh, g_fgwh);
    cudaGetSymbolAddress((void**)&whhh, g_whhh);
    cudaGetSymbolAddress((void**)&ogwh, g_ogwh);
    cudaGetSymbolAddress((void**)&wgih, g_wgih);
    cudaGetSymbolAddress((void**)&gth,  g_gth);
    cudaGetSymbolAddress((void**)&udh,  g_udh);
    cudaGetSymbolAddress((void**)&gih,  g_gih);
    cudaGetSymbolAddress((void**)&ghh,  g_ghh);
    cudaGetSymbolAddress((void**)&iph,  g_iph);
    cudaGetSymbolAddress((void**)&wvh,  g_wvh);
    cudaGetSymbolAddress((void**)&oph,  g_oph);
    cudaGetSymbolAddress((void**)&wihh, g_wihh);
    cudaGetSymbolAddress((void**)&m1h,  g_m1h);
    cudaGetSymbolAddress((void**)&m2h,  g_m2h);

    cudaFuncSetAttribute(h16_gemm, cudaFuncAttributeMaxDynamicSharedMemorySize, SMEM_DYN);

    const Seg Z = {nullptr, 0, nullptr, 0, 0};
    const int NSQ = CTX_DIM * CTX_DIM;

    // launches #0-2: staging needed by FG
    f2h_kernel<<<(BB * IN_DIM / 8) / 256, 256>>>((const float4*)input, (uint4*)inh, BB * IN_DIM / 8);
    f2h_kernel<<<(BB * MEM_DIM / 8) / 256, 256>>>((const float4*)prev, (uint4*)pvh, BB * MEM_DIM / 8);
    f2h_kernel<<<(MEM_DIM * (MEM_DIM + IN_DIM) / 8) / 256, 256>>>(
        (const float4*)fg_w, (uint4*)fgwh, MEM_DIM * (MEM_DIM + IN_DIM) / 8);

    // launch #3 (ncu capture target): FG GEMM
    // gth = rn16(prev * sigmoid(prev@fgA^T + input@fgB^T + fg_b))
    {
        Seg a = {pvh, MEM_DIM, fgwh,           MEM_DIM + IN_DIM, MEM_DIM};
        Seg b = {inh, IN_DIM,  fgwh + MEM_DIM, MEM_DIM + IN_DIM, IN_DIM};
        h16_gemm<<<dim3(MEM_DIM / BN, BB / BM), 256, SMEM_DYN>>>(
            a, b, Z, fg_b, prev, nullptr, gth, MEM_DIM, 1, 0);
    }

    // remaining staging + bias folds
    f2h_kernel<<<(NGATE * MEM_DIM / 8) / 256, 256>>>((const float4*)w_hh, (uint4*)whhh, NGATE * MEM_DIM / 8);
    f2h_kernel<<<(MEM_DIM * MEM_DIM / 8) / 256, 256>>>((const float4*)og_w, (uint4*)ogwh, MEM_DIM * MEM_DIM / 8);
    gemv_kernel<<<CTX_DIM / 8, 256>>>(wv,         CTX_DIM, ip_b, bv,         b1, CTX_DIM, CTX_DIM);
    gemv_kernel<<<CTX_DIM / 8, 256>>>(out_proj_w, CTX_DIM, b1,   out_proj_b, b2, CTX_DIM, CTX_DIM);
    gemv_kernel<<<NGATE / 8, 256>>>(w_ih, CTX_DIM, b2, b_ih, bgi, NGATE, CTX_DIM);

    // GH (f16 out): ghh = rn16(gated @ w_hh^T + b_hh)
    {
        Seg a = {gth, MEM_DIM, whhh, MEM_DIM, MEM_DIM};
        h16_gemm<<<dim3(NGATE / BN, BB / BM), 256, SMEM_DYN>>>(
            a, Z, Z, b_hh, nullptr, nullptr, ghh, NGATE, 0, 0);
    }

    // ---- weight folds: single-pass fp16, split-K Z=4, f16 intermediates ----
    transpose_h_kernel<<<dim3(IN_DIM / 32, CTX_DIM / 32), dim3(32, 8)>>>(ip_w, iph, CTX_DIM, IN_DIM);
    f2h_kernel<<<(NSQ / 8) / 256, 256>>>((const float4*)wv, (uint4*)wvh, NSQ / 8);
    {   // M1T[IN,CTX] = ip_w^T @ wv^T
        Seg a = {iph, CTX_DIM, wvh, CTX_DIM, CTX_DIM};
        h16_gemm<<<dim3(CTX_DIM / BN, IN_DIM / BM, ZSPLIT), 256, SMEM_DYN>>>(
            a, Z, Z, nullptr, nullptr, part, nullptr, CTX_DIM, 0, IN_DIM);
        reduce_zh_kernel<<<(NSQ / 4) / 256, 256>>>(
            (const float4*)part, (uint2*)m1h, NSQ / 4, ZSPLIT, NSQ / 4);
    }
    f2h_kernel<<<(NSQ / 8) / 256, 256>>>((const float4*)out_proj_w, (uint4*)oph, NSQ / 8);
    {   // M2T[IN,CTX] = M1T @ out_proj_w^T
        Seg a = {m1h, CTX_DIM, oph, CTX_DIM, CTX_DIM};
        h16_gemm<<<dim3(CTX_DIM / BN, IN_DIM / BM, ZSPLIT), 256, SMEM_DYN>>>(
            a, Z, Z, nullptr, nullptr, part, nullptr, CTX_DIM, 0, IN_DIM);
        reduce_zh_kernel<<<(NSQ / 4) / 256, 256>>>(
            (const float4*)part, (uint2*)m2h, NSQ / 4, ZSPLIT, NSQ / 4);
    }
    f2h_kernel<<<(NGATE * CTX_DIM / 8) / 256, 256>>>((const float4*)w_ih, (uint4*)wihh, NGATE * CTX_DIM / 8);
    {   // WGIH[NGATE,IN] = rn16(w_ih @ M2T^T)
        Seg a = {wihh, CTX_DIM, m2h, CTX_DIM, CTX_DIM};
        h16_gemm<<<dim3(IN_DIM / BN, NGATE / BM, ZSPLIT), 256, SMEM_DYN>>>(
            a, Z, Z, nullptr, nullptr, part, nullptr, IN_DIM, 0, NGATE);
        reduce_zh_kernel<<<(NGATE * IN_DIM / 4) / 256, 256>>>(
            (const float4*)part, (uint2*)wgih, NGATE * IN_DIM / 4, ZSPLIT, NGATE * IN_DIM / 4);
    }

    // GI (f16 out): gih = rn16(input @ WGI^T + bgi)
    {
        Seg a = {inh, IN_DIM, wgih, IN_DIM, IN_DIM};
        h16_gemm<<<dim3(NGATE / BN, BB / BM), 256, SMEM_DYN>>>(
            a, Z, Z, bgi, nullptr, nullptr, gih, NGATE, 0, 0);
    }
    // GRU elementwise -> upd (f32) + udh (f16)
    ew_gru_kernel<<<(BB * MEM_DIM / 4) / 256, 256>>>(
        (const uint2*)gih, (const uint2*)ghh, (const uint2*)gth,
        (float4*)upd, (uint2*)udh, BB * MEM_DIM / 4);
    // out = upd * sigmoid(upd @ og_w^T + og_b)
    {
        Seg a = {udh, MEM_DIM, ogwh, MEM_DIM, MEM_DIM};
        h16_gemm<<<dim3(MEM_DIM / BN, BB / BM), 256, SMEM_DYN>>>(
            a, Z, Z, og_b, upd, out, nullptr, MEM_DIM, 1, 0);
    }
    // attention weights: softmax over single key == 1.0
    int tail = out_size - BB * MEM_DIM;
    if (tail > 0)
        fill_ones_kernel<<<(tail + 255) / 256, 256>>>(out + BB * MEM_DIM, tail);
}